// round 14
// baseline (speedup 1.0000x reference)
#include <cuda_runtime.h>
#include <cuda_bf16.h>
#include <cstdint>

// ---------------- problem constants ----------------
#define BATCH 16
#define TLEN  4095
#define LSEQ  4096          // TLEN + 1
#define NTOK  (BATCH*LSEQ)  // 65536
#define OBSD  128
#define HID   256
#define NHEAD 8
#define DHEAD 32
#define FFD   1024
#define NLAY  4
#define QKVW  (3*HID)       // 768
#define KSPLIT 8
#define KTOT   32
#define KEPS  1e-3f
#define LNEPS 1e-6f

// ---------------- device scratch (fp32 activations) ----------------
__device__ float g_x  [(size_t)NTOK*HID];
__device__ float g_qkv[(size_t)NTOK*QKVW];
__device__ float g_a  [(size_t)NTOK*HID];
__device__ float g_z  [(size_t)NTOK*HID];
__device__ float g_f  [(size_t)NTOK*FFD];
__device__ float g_ins[(size_t)(BATCH*TLEN)*OBSD];
__device__ float g_kvpart[(size_t)KTOT*BATCH*NHEAD*DHEAD*DHEAD];
__device__ float g_kspart[(size_t)KTOT*BATCH*NHEAD*DHEAD];
__device__ float g_weff [(size_t)BATCH*HID*HID];   // tf32-rounded WT[c][d] per batch
__device__ float g_weff2[(size_t)BATCH*HID*HID];   // fp32 [b][d][c] for last-mile
__device__ float g_a0[BATCH*HID];

#define WT_EMB_SZ   (HID*OBSD)
#define WT_LAYER_SZ (4*HID*HID + 2*HID*FFD)
#define WT_TOTAL    (WT_EMB_SZ + NLAY*WT_LAYER_SZ)
__device__ float g_wt[WT_TOTAL];    // transposed tf32-rounded weights WT[N][K]

static inline int cdiv(int a, int b) { return (a + b - 1) / b; }

// ---------------- helpers ----------------
__device__ __forceinline__ uint32_t smem_u32(const void* p) {
    uint32_t a;
    asm("{ .reg .u64 t; cvta.to.shared.u64 t, %1; cvt.u32.u64 %0, t; }" : "=r"(a) : "l"(p));
    return a;
}
__device__ __forceinline__ float tfr(float x) {
    uint32_t r;
    asm("cvt.rna.tf32.f32 %0, %1;" : "=r"(r) : "f"(x));
    return __uint_as_float(r);
}

#define MMA_TF32(d, a0, a1, a2, a3, b0, b1)                                \
    asm volatile("mma.sync.aligned.m16n8k8.row.col.f32.tf32.tf32.f32 "     \
                 "{%0,%1,%2,%3},{%4,%5,%6,%7},{%8,%9},{%0,%1,%2,%3};"      \
                 : "+f"((d)[0]), "+f"((d)[1]), "+f"((d)[2]), "+f"((d)[3])  \
                 : "r"(a0), "r"(a1), "r"(a2), "r"(a3), "r"(b0), "r"(b1))

__device__ __forceinline__ void cpa16(uint32_t dst, const void* src, int sz) {
    asm volatile("cp.async.cg.shared.global [%0], [%1], 16, %2;"
                 :: "r"(dst), "l"(__cvta_generic_to_global(src)), "r"(sz));
}

// ---------------- single-launch weight conversion (transpose + tf32 round) ----
__global__ void ta_wconv_all(const float* __restrict__ embW,
                             const float* __restrict__ Wq, const float* __restrict__ Wk,
                             const float* __restrict__ Wv, const float* __restrict__ Wo,
                             const float* __restrict__ W1, const float* __restrict__ W2,
                             float* __restrict__ wt) {
    const int seg = blockIdx.y;
    const float* src;
    int K, N;
    size_t dst;
    if (seg == 0) {
        src = embW; K = OBSD; N = HID; dst = 0;
    } else {
        const int l = (seg - 1) / 6, m = (seg - 1) % 6;
        const size_t base = WT_EMB_SZ + (size_t)l * WT_LAYER_SZ;
        switch (m) {
            case 0: src = Wq + (size_t)l*HID*HID; K = HID; N = HID; dst = base;          break;
            case 1: src = Wk + (size_t)l*HID*HID; K = HID; N = HID; dst = base + 65536;  break;
            case 2: src = Wv + (size_t)l*HID*HID; K = HID; N = HID; dst = base + 131072; break;
            case 3: src = Wo + (size_t)l*HID*HID; K = HID; N = HID; dst = base + 196608; break;
            case 4: src = W1 + (size_t)l*HID*FFD; K = HID; N = FFD; dst = base + 262144; break;
            default:src = W2 + (size_t)l*FFD*HID; K = FFD; N = HID; dst = base + 524288; break;
        }
    }
    int i = blockIdx.x * 256 + threadIdx.x;
    if (i >= N * K) return;
    int n = i / K, k = i - n * K;
    wt[dst + i] = tfr(src[(size_t)k * N + n]);
}

// ---------------- split ins + init hidden row (tf32 round) ----------------
__global__ void ta_prep(const float* __restrict__ ins,
                        const float* __restrict__ hs,
                        const unsigned char* __restrict__ resets,
                        float* __restrict__ IF, float* __restrict__ X) {
    const int nIns = BATCH * TLEN * OBSD;
    int i = blockIdx.x * 256 + threadIdx.x;
    if (i < nIns) {
        IF[i] = tfr(ins[i]);
    } else {
        int j = i - nIns;
        if (j < BATCH * HID) {
            int b = j >> 8, c = j & 255;
            float v = resets[b] ? 0.f : hs[b*HID + c];
            X[(size_t)b*LSEQ*HID + c] = tfr(v);
        }
    }
}

// ---------------- single-pass TF32 MMA GEMM ----------------
// Block tile 128x64, 8 warps (4 row x 2 col), warp tile 32x32 (m16n8k8 frags).
// smem: A 128x36 fl (18432B) + B 64x36 fl (9216B) = 27648B/stage, 3 stages.
// Swizzle: phys_col = col ^ ((row&3)<<3), row stride 36 floats.
// flags: bit0 embRemap, bit1 qkvMode, bit2 batchedB, bit3 colOff+4, bit4 roundOut
__global__ __launch_bounds__(256, 2)
void ta_gemm_tf32(const float* __restrict__ A, const float* __restrict__ B,
                  const float* __restrict__ bias0, const float* __restrict__ bias1,
                  const float* __restrict__ bias2,
                  float* __restrict__ C,
                  int M, int K, int N, int epi, int flags) {
    extern __shared__ char smem[];
    const uint32_t smu = smem_u32(smem);

    const int tid  = threadIdx.x;
    const int wid  = tid >> 5;
    const int lane = tid & 31;
    const int wr   = wid >> 1;       // 0..3
    const int wc   = wid & 1;        // 0..1
    const int rowBase = blockIdx.y * 128;
    const int colBase = (blockIdx.x + ((flags & 8) ? 4 : 0)) * 64;

    if (flags & 4) {
        const size_t boff = (size_t)(rowBase >> 12) * HID * HID;
        B += boff;
    }

    // cp.async mapping
    const int rA = tid >> 1;             // 0..127
    const int qA = (tid & 1) * 4;        // chunk base 0 or 4
    const int rB = tid >> 2;             // 0..63
    const int qB = tid & 3;              // chunks qB, qB+4
    const uint32_t sxA = (uint32_t)((rA & 3) * 2);   // chunk-unit xor
    const uint32_t sxB = (uint32_t)((rB & 3) * 2);

    float acc[2][4][4] = {};

    auto load_stage = [&](int st, int kt) {
        const uint32_t sb = smu + (uint32_t)st * 27648u;
        const int kOff = kt * 32;
        // A: 4 chunks
        {
            const int grow = rowBase + rA;
            const int sz = (grow < M) ? 16 : 0;
            const float* srcr = A + (size_t)(sz ? grow : 0) * K + kOff;
            const uint32_t db = sb + (uint32_t)(rA * 144);
            #pragma unroll
            for (int j = 0; j < 4; j++) {
                const uint32_t q = (uint32_t)(qA + j);
                cpa16(db + ((q ^ sxA) << 4), srcr + q * 4, sz);
            }
        }
        // B: 2 chunks
        {
            const float* srcr = B + (size_t)(colBase + rB) * K + kOff;
            const uint32_t db = sb + 18432u + (uint32_t)(rB * 144);
            cpa16(db + (((uint32_t)qB       ^ sxB) << 4), srcr + qB * 4,       16);
            cpa16(db + (((uint32_t)(qB + 4) ^ sxB) << 4), srcr + (qB + 4) * 4, 16);
        }
        asm volatile("cp.async.commit_group;");
    };

    const uint32_t r4 = (uint32_t)(lane >> 2);
    const uint32_t c4 = (uint32_t)(lane & 3);
    const uint32_t sx = (r4 & 3) << 3;   // element-unit xor (bits 3-4)

    auto compute = [&](int st) {
        const char* sb = smem + (size_t)st * 27648u;
        const char* bbase = sb + 18432;
        #pragma unroll
        for (int ks = 0; ks < 4; ks++) {
            const uint32_t kc = (uint32_t)(ks * 8);
            uint32_t b[4][2];
            #pragma unroll
            for (int nj = 0; nj < 4; nj++) {
                const uint32_t n = (uint32_t)(wc * 32 + nj * 8) + r4;
                const uint32_t c0_ = kc + c4;
                b[nj][0] = *(const uint32_t*)(bbase + (n * 36 + ((c0_    ) ^ sx)) * 4);
                b[nj][1] = *(const uint32_t*)(bbase + (n * 36 + ((c0_ + 4) ^ sx)) * 4);
            }
            #pragma unroll
            for (int mi = 0; mi < 2; mi++) {
                const uint32_t r0_ = (uint32_t)(wr * 32 + mi * 16) + r4;
                const uint32_t r1_ = r0_ + 8;
                const uint32_t c0_ = kc + c4;
                uint32_t a0 = *(const uint32_t*)(sb + (r0_ * 36 + ((c0_    ) ^ sx)) * 4);
                uint32_t a1 = *(const uint32_t*)(sb + (r1_ * 36 + ((c0_    ) ^ sx)) * 4);
                uint32_t a2 = *(const uint32_t*)(sb + (r0_ * 36 + ((c0_ + 4) ^ sx)) * 4);
                uint32_t a3 = *(const uint32_t*)(sb + (r1_ * 36 + ((c0_ + 4) ^ sx)) * 4);
                #pragma unroll
                for (int nj = 0; nj < 4; nj++)
                    MMA_TF32(acc[mi][nj], a0, a1, a2, a3, b[nj][0], b[nj][1]);
            }
        }
    };

    const int nk = K >> 5;
    load_stage(0, 0);
    load_stage(1, 1);
    int cs = 0, ls = 2;
    for (int kt = 0; kt < nk; kt++) {
        if (kt == nk - 1) asm volatile("cp.async.wait_group 0;");
        else              asm volatile("cp.async.wait_group 1;");
        __syncthreads();
        if (kt + 2 < nk) {
            load_stage(ls, kt + 2);
            ls = (ls == 2) ? 0 : ls + 1;
        }
        compute(cs);
        cs = (cs == 2) ? 0 : cs + 1;
    }

    // ---- epilogue
    const bool embRemap = flags & 1;
    const bool qkvMode  = flags & 2;
    const bool roundOut = flags & 16;
    const float* bptr = bias0;
    int ep = epi;
    if (qkvMode) {
        int seg = colBase >> 8;
        bptr = (seg == 0) ? bias0 : (seg == 1) ? bias1 : bias2;
        ep = (seg < 2) ? 1 : 0;
    }
    #pragma unroll
    for (int mi = 0; mi < 2; mi++) {
        #pragma unroll
        for (int duo = 0; duo < 2; duo++) {
            const int row = rowBase + wr * 32 + mi * 16 + (int)r4 + duo * 8;
            if (row >= M) continue;
            size_t orow = (size_t)row;
            if (embRemap) {
                int b = row / TLEN;
                orow = (size_t)b * LSEQ + 1 + (row - b * TLEN);
            }
            #pragma unroll
            for (int nj = 0; nj < 4; nj++) {
                const int col = colBase + wc * 32 + nj * 8 + 2 * (int)c4;
                const int bcol = qkvMode ? (col & 255) : col;
                float v0 = acc[mi][nj][duo * 2 + 0] + bptr[bcol];
                float v1 = acc[mi][nj][duo * 2 + 1] + bptr[bcol + 1];
                if (ep == 1)      { v0 = fmaxf(v0, 0.f) + KEPS; v1 = fmaxf(v1, 0.f) + KEPS; }
                else if (ep == 2) { v0 = fmaxf(v0, 0.f);        v1 = fmaxf(v1, 0.f); }
                if (roundOut) { v0 = tfr(v0); v1 = tfr(v1); }
                *(float2*)(C + orow * N + col) = make_float2(v0, v1);
            }
        }
    }
}

// ---------------- kv partials: register-tiled (4x4 per thread) ----------------
__global__ void ta_kv_reduce(const float* __restrict__ QKV,
                             float* __restrict__ KVp, float* __restrict__ KSp) {
    const int s = blockIdx.x, h = blockIdx.y, b = blockIdx.z;
    const int tid = threadIdx.x;

    __shared__ float kp[32][36];
    __shared__ float vv[32][36];

    const size_t rowBase = (size_t)b * LSEQ + (size_t)s * (LSEQ / KSPLIT);

    const int row_ = tid >> 3;
    const int part = tid & 7;
    const int isV  = part >> 2;
    const int cseg = (part & 3) * 8;
    float* stDst = (isV ? &vv[row_][cseg] : &kp[row_][cseg]);

    const int tsub = tid >> 6;
    const int t64  = tid & 63;
    const int tm4  = (t64 >> 3) << 2;
    const int td4  = (t64 & 7) << 2;
    const bool ksaOwner = ((t64 & 7) == 0);

    float acc[4][4] = {};
    float ksa[4] = {0.f, 0.f, 0.f, 0.f};

    for (int c0 = 0; c0 < LSEQ / KSPLIT; c0 += 32) {
        {
            const size_t g = (rowBase + c0 + row_) * QKVW
                           + (isV ? 2*HID : HID) + h * DHEAD + cseg;
            float4 p0 = *(const float4*)(QKV + g);
            float4 p1 = *(const float4*)(QKV + g + 4);
            *(float4*)(stDst)     = p0;
            *(float4*)(stDst + 4) = p1;
        }
        __syncthreads();
        #pragma unroll
        for (int q = 0; q < 8; q++) {
            const int l = tsub * 8 + q;
            float4 kq = *(const float4*)&kp[l][tm4];
            float4 vq = *(const float4*)&vv[l][td4];
            float km[4] = {kq.x, kq.y, kq.z, kq.w};
            float vd[4] = {vq.x, vq.y, vq.z, vq.w};
            #pragma unroll
            for (int i = 0; i < 4; i++)
                #pragma unroll
                for (int j = 0; j < 4; j++)
                    acc[i][j] += km[i] * vd[j];
            if (ksaOwner) {
                #pragma unroll
                for (int i = 0; i < 4; i++) ksa[i] += km[i];
            }
        }
        __syncthreads();
    }

    const int bh = b * NHEAD + h;
    const size_t slot = (size_t)(s * 4 + tsub) * BATCH * NHEAD + bh;
    #pragma unroll
    for (int i = 0; i < 4; i++)
        *(float4*)&KVp[slot * 1024 + (tm4 + i) * 32 + td4] =
            make_float4(acc[i][0], acc[i][1], acc[i][2], acc[i][3]);
    if (ksaOwner)
        *(float4*)&KSp[slot * 32 + tm4] = make_float4(ksa[0], ksa[1], ksa[2], ksa[3]);
}

// ---------------- WeffT = blockdiag(kv) @ Wo ----------------
__global__ void ta_weff(const float* __restrict__ KVp, const float* __restrict__ Wo,
                        float* __restrict__ WE, float* __restrict__ W2f) {
    const int h = blockIdx.x, b = blockIdx.y;
    const int tid = threadIdx.x;
    const int bh = b * NHEAD + h;
    __shared__ float kvs[DHEAD*DHEAD];
    for (int i = tid; i < DHEAD*DHEAD; i += 256) {
        float v = 0.f;
        #pragma unroll
        for (int s = 0; s < KTOT; s++)
            v += KVp[((size_t)s * BATCH*NHEAD + bh) * 1024 + i];
        kvs[i] = v;
    }
    __syncthreads();

    float wcol[DHEAD];
    #pragma unroll
    for (int d = 0; d < DHEAD; d++)
        wcol[d] = Wo[((size_t)h*DHEAD + d)*HID + tid];

    for (int m = 0; m < DHEAD; m++) {
        const float4* k4 = (const float4*)&kvs[m*DHEAD];
        float a0 = 0.f;
        #pragma unroll
        for (int q = 0; q < 8; q++) {
            float4 kk = k4[q];
            a0 += kk.x*wcol[4*q] + kk.y*wcol[4*q+1] + kk.z*wcol[4*q+2] + kk.w*wcol[4*q+3];
        }
        WE[((size_t)b*HID + tid)*HID + h*DHEAD + m] = tfr(a0);        // WT[c][d]
        W2f[((size_t)b*HID + h*DHEAD + m)*HID + tid] = a0;            // [d][c]
    }
}

// ---------------- qp' = qp / (qp . ksum), tf32-rounded output ----------------
__global__ void ta_qpscale(const float* __restrict__ QKV, const float* __restrict__ KSp,
                           float* __restrict__ Aout) {
    __shared__ float kss[HID];
    const int b = blockIdx.y;
    const int tokBase = blockIdx.x * 32;
    const int tid = threadIdx.x;
    {
        const int h2 = tid >> 5, m = tid & 31;
        float v = 0.f;
        #pragma unroll
        for (int s = 0; s < KTOT; s++)
            v += KSp[((size_t)s * BATCH*NHEAD + b*NHEAD + h2) * 32 + m];
        kss[tid] = v;
    }
    __syncthreads();

    const int tok = tokBase + (tid >> 3);
    const int h   = tid & 7;
    const size_t qrow = ((size_t)b * LSEQ + tok) * QKVW + h * DHEAD;
    const size_t arow = ((size_t)b * LSEQ + tok) * HID  + h * DHEAD;

    float qv[DHEAD];
    #pragma unroll
    for (int g = 0; g < 8; g++) {
        float4 t = *(const float4*)(QKV + qrow + g*4);
        qv[g*4+0] = t.x; qv[g*4+1] = t.y; qv[g*4+2] = t.z; qv[g*4+3] = t.w;
    }
    float den = 0.f;
    #pragma unroll
    for (int m = 0; m < DHEAD; m++) den += qv[m] * kss[h*DHEAD + m];
    const float inv = 1.f / den;
    #pragma unroll
    for (int g = 0; g < 8; g++) {
        *(float4*)(Aout + arow + g*4) = make_float4(
            tfr(qv[g*4+0]*inv), tfr(qv[g*4+1]*inv),
            tfr(qv[g*4+2]*inv), tfr(qv[g*4+3]*inv));
    }
}

// ---------------- X = LN(2*Z)*scale + bias, tf32-rounded ----------------
__global__ void ta_ln2(const float* __restrict__ Z,
                       const float* __restrict__ sc, const float* __restrict__ bi,
                       float* __restrict__ X) {
    const int row  = blockIdx.x * 8 + threadIdx.y;
    const int lane = threadIdx.x;
    const size_t base = (size_t)row * HID + lane * 8;

    float v[8];
    {
        float4 a = *(const float4*)(Z + base);
        float4 c = *(const float4*)(Z + base + 4);
        v[0]=a.x; v[1]=a.y; v[2]=a.z; v[3]=a.w;
        v[4]=c.x; v[5]=c.y; v[6]=c.z; v[7]=c.w;
    }
    float sum = 0.f;
    #pragma unroll
    for (int j = 0; j < 8; j++) { v[j] *= 2.f; sum += v[j]; }
    #pragma unroll
    for (int o = 16; o; o >>= 1) sum += __shfl_xor_sync(0xffffffffu, sum, o);
    const float mean = sum * (1.f / HID);

    float vs = 0.f;
    #pragma unroll
    for (int j = 0; j < 8; j++) { float d = v[j] - mean; vs += d * d; }
    #pragma unroll
    for (int o = 16; o; o >>= 1) vs += __shfl_xor_sync(0xffffffffu, vs, o);
    const float rr = rsqrtf(vs * (1.f / HID) + LNEPS);

    float o8[8];
    #pragma unroll
    for (int j = 0; j < 8; j++) {
        int c = lane * 8 + j;
        o8[j] = tfr((v[j] - mean) * rr * sc[c] + bi[c]);
    }
    *(float4*)(X + base)     = make_float4(o8[0], o8[1], o8[2], o8[3]);
    *(float4*)(X + base + 4) = make_float4(o8[4], o8[5], o8[6], o8[7]);
}

// ---------------- last layer token-0 kernels (fp32) ----------------
__global__ void ta_lastq(const float* __restrict__ X,
                         const float* __restrict__ Wq3, const float* __restrict__ bq3,
                         const float* __restrict__ KSp, float* __restrict__ A0) {
    const int b = blockIdx.x, c = threadIdx.x;
    __shared__ float xs[HID], qps[HID], kss[HID];
    xs[c] = X[(size_t)b*LSEQ*HID + c];
    {
        const int h2 = c >> 5, m = c & 31;
        float v = 0.f;
        #pragma unroll
        for (int s = 0; s < KTOT; s++)
            v += KSp[((size_t)s * BATCH*NHEAD + b*NHEAD + h2) * 32 + m];
        kss[c] = v;
    }
    __syncthreads();
    float q = bq3[c];
    #pragma unroll 8
    for (int d = 0; d < HID; d++) q += xs[d] * Wq3[(size_t)d*HID + c];
    float qp = fmaxf(q, 0.f) + KEPS;
    qps[c] = qp;
    __syncthreads();
    const int h = c >> 5;
    float den = 0.f;
    #pragma unroll
    for (int m = 0; m < DHEAD; m++) den += qps[h*DHEAD + m] * kss[h*DHEAD + m];
    A0[b*HID + c] = qp / den;
}

__global__ void ta_lastmile(const float* __restrict__ A0, const float* __restrict__ W2f,
                            const float* __restrict__ bo3,
                            const float* __restrict__ ln1s3, const float* __restrict__ ln1b3,
                            const float* __restrict__ W1_3, const float* __restrict__ b1_3,
                            const float* __restrict__ W2_3, const float* __restrict__ b2_3,
                            const float* __restrict__ ln2s3, const float* __restrict__ ln2b3,
                            const float* __restrict__ qpW, const float* __restrict__ qpb,
                            float* __restrict__ out) {
    const int b = blockIdx.x, c = threadIdx.x;
    const int wid = c >> 5, lane = c & 31;
    __shared__ float a0[HID], x1[HID], f[FFD], xo[HID], sred[16];

    a0[c] = A0[b*HID + c];
    __syncthreads();

    float o = bo3[c];
    const float* w = W2f + (size_t)b*HID*HID;
    #pragma unroll 8
    for (int d = 0; d < HID; d++) o += a0[d] * w[(size_t)d*HID + c];
    float v = 2.f * o;

    {
        float s = v, q = v * v;
        #pragma unroll
        for (int off = 16; off; off >>= 1) {
            s += __shfl_xor_sync(0xffffffffu, s, off);
            q += __shfl_xor_sync(0xffffffffu, q, off);
        }
        if (lane == 0) { sred[wid] = s; sred[8 + wid] = q; }
        __syncthreads();
        float ts = 0.f, tq = 0.f;
        #pragma unroll
        for (int i = 0; i < 8; i++) { ts += sred[i]; tq += sred[8 + i]; }
        const float mean = ts * (1.f / HID);
        const float var  = tq * (1.f / HID) - mean * mean;
        const float rr   = rsqrtf(var + LNEPS);
        x1[c] = (v - mean) * rr * ln1s3[c] + ln1b3[c];
        __syncthreads();
    }

    #pragma unroll
    for (int jj = 0; jj < 4; jj++) {
        const int j = c + jj * 256;
        float s = b1_3[j];
        #pragma unroll 8
        for (int d = 0; d < HID; d++) s += x1[d] * W1_3[(size_t)d*FFD + j];
        f[j] = fmaxf(s, 0.f);
    }
    __syncthreads();

    float z = b2_3[c];
    #pragma unroll 8
    for (int j = 0; j < FFD; j++) z += f[j] * W2_3[(size_t)j*HID + c];
    float v2 = 2.f * z;

    {
        float s = v2, q = v2 * v2;
        #pragma unroll
        for (int off = 16; off; off >>= 1) {
            s += __shfl_xor_sync(0xffffffffu, s, off);
            q += __shfl_xor_sync(0xffffffffu, q, off);
        }
        __syncthreads();
        if (lane == 0) { sred[wid] = s; sred[8 + wid] = q; }
        __syncthreads();
        float ts = 0.f, tq = 0.f;
        #pragma unroll
        for (int i = 0; i < 8; i++) { ts += sred[i]; tq += sred[8 + i]; }
        const float mean = ts * (1.f / HID);
        const float var  = tq * (1.f / HID) - mean * mean;
        const float rr   = rsqrtf(var + LNEPS);
        xo[c] = (v2 - mean) * rr * ln2s3[c] + ln2b3[c];
    }
    out[b*HID + c] = xo[c];
    __syncthreads();

    if (c < 32) {
        float s = qpb[c];
        #pragma unroll 8
        for (int d = 0; d < HID; d++) s += xo[d] * qpW[d*32 + c];
        out[BATCH*HID + b*32 + c] = s;
    }
}

// ---------------- launcher ----------------
extern "C" void kernel_launch(void* const* d_in, const int* in_sizes, int n_in,
                              void* d_out, int out_size) {
    const float* hidden = (const float*)d_in[0];
    const float* ins    = (const float*)d_in[1];
    const unsigned char* resets = (const unsigned char*)d_in[2];
    const float* embW = (const float*)d_in[3];
    const float* embb = (const float*)d_in[4];
    const float* Wq = (const float*)d_in[5];
    const float* bq = (const float*)d_in[6];
    const float* Wk = (const float*)d_in[7];
    const float* bk = (const float*)d_in[8];
    const float* Wv = (const float*)d_in[9];
    const float* bv = (const float*)d_in[10];
    const float* Wo = (const float*)d_in[11];
    const float* bo = (const float*)d_in[12];
    const float* ln1s = (const float*)d_in[13];
    const float* ln1b = (const float*)d_in[14];
    const float* W1 = (const float*)d_in[15];
    const float* b1 = (const float*)d_in[16];
    const float* W2 = (const float*)d_in[17];
    const float* b2 = (const float*)d_in[18];
    const float* ln2s = (const float*)d_in[19];
    const float* ln2b = (const float*)d_in[20];
    const float* qpW = (const float*)d_in[21];
    const float* qpb = (const float*)d_in[22];

    float *x, *qkv, *a, *z, *f, *insf, *wt, *we, *w2f, *kvp, *ksp, *a0;
    cudaGetSymbolAddress((void**)&x,    g_x);
    cudaGetSymbolAddress((void**)&qkv,  g_qkv);
    cudaGetSymbolAddress((void**)&a,    g_a);
    cudaGetSymbolAddress((void**)&z,    g_z);
    cudaGetSymbolAddress((void**)&f,    g_f);
    cudaGetSymbolAddress((void**)&insf, g_ins);
    cudaGetSymbolAddress((void**)&wt,   g_wt);
    cudaGetSymbolAddress((void**)&we,   g_weff);
    cudaGetSymbolAddress((void**)&w2f,  g_weff2);
    cudaGetSymbolAddress((void**)&kvp,  g_kvpart);
    cudaGetSymbolAddress((void**)&ksp,  g_kspart);
    cudaGetSymbolAddress((void**)&a0,   g_a0);

    const int GEMM_SMEM = 3 * 27648;   // 82944
    cudaFuncSetAttribute(ta_gemm_tf32, cudaFuncAttributeMaxDynamicSharedMemorySize, GEMM_SMEM);

    ta_wconv_all<<<dim3(1024, 25), 256>>>(embW, Wq, Wk, Wv, Wo, W1, W2, wt);
    {
        int n = BATCH*TLEN*OBSD + BATCH*HID;
        ta_prep<<<cdiv(n,256), 256>>>(ins, hidden, resets, insf, x);
    }
    {
        int M = BATCH * TLEN;
        ta_gemm_tf32<<<dim3(HID/64, cdiv(M,128)), 256, GEMM_SMEM>>>(
            insf, wt, embb, embb, embb, x, M, OBSD, HID, 0, 1 | 16);
    }

    const dim3 gqkv(QKVW/64, NTOK/128);  // (12, 512)
    const dim3 gkv (8,       NTOK/128);  // kv-only: tiles 4..11
    const dim3 g256(HID/64,  NTOK/128);  // (4, 512)
    const dim3 gff (FFD/64,  NTOK/128);  // (16, 512)

    for (int l = 0; l < NLAY; l++) {
        const bool last = (l == NLAY - 1);
        size_t base = WT_EMB_SZ + (size_t)l * WT_LAYER_SZ;
        const float *qkvw = wt + base;
        const float *w1t  = wt + base + 262144;
        const float *w2t  = wt + base + 524288;

        if (!last) {
            ta_gemm_tf32<<<gqkv, 256, GEMM_SMEM>>>(x, qkvw,
                                                   bq + l*HID, bk + l*HID, bv + l*HID,
                                                   qkv, NTOK, HID, QKVW, 0, 2);
        } else {
            ta_gemm_tf32<<<gkv, 256, GEMM_SMEM>>>(x, qkvw,
                                                  bq + l*HID, bk + l*HID, bv + l*HID,
                                                  qkv, NTOK, HID, QKVW, 0, 2 | 8);
        }
        ta_kv_reduce<<<dim3(KSPLIT, NHEAD, BATCH), 256>>>(qkv, kvp, ksp);
        ta_weff<<<dim3(NHEAD, BATCH), 256>>>(kvp, Wo + (size_t)l*HID*HID, we, w2f);

        if (!last) {
            ta_qpscale<<<dim3(LSEQ/32, BATCH), 256>>>(qkv, ksp, a);
            ta_gemm_tf32<<<g256, 256, GEMM_SMEM>>>(a, we,
                                                   bo + l*HID, bo + l*HID, bo + l*HID,
                                                   z, NTOK, HID, HID, 0, 4);
            ta_ln2<<<NTOK/8, dim3(32,8)>>>(z, ln1s + l*HID, ln1b + l*HID, x);

            ta_gemm_tf32<<<gff, 256, GEMM_SMEM>>>(x, w1t,
                                                  b1 + l*FFD, b1 + l*FFD, b1 + l*FFD,
                                                  f, NTOK, HID, FFD, 2, 16);
            ta_gemm_tf32<<<g256, 256, GEMM_SMEM>>>(f, w2t,
                                                   b2 + l*HID, b2 + l*HID, b2 + l*HID,
                                                   z, NTOK, FFD, HID, 0, 0);
            ta_ln2<<<NTOK/8, dim3(32,8)>>>(z, ln2s + l*HID, ln2b + l*HID, x);
        } else {
            ta_lastq<<<BATCH, 256>>>(x, Wq + (size_t)l*HID*HID, bq + l*HID, ksp, a0);
            ta_lastmile<<<BATCH, 256>>>(a0, w2f, bo + l*HID,
                                        ln1s + l*HID, ln1b + l*HID,
                                        W1 + (size_t)l*HID*FFD, b1 + l*FFD,
                                        W2 + (size_t)l*FFD*HID, b2 + l*HID,
                                        ln2s + l*HID, ln2b + l*HID,
                                        qpW, qpb, (float*)d_out);
        }
    }
}

// round 15
// speedup vs baseline: 1.2493x; 1.2493x over previous
#include <cuda_runtime.h>
#include <cuda_bf16.h>
#include <cstdint>

// ---------------- problem constants ----------------
#define BATCH 16
#define TLEN  4095
#define LSEQ  4096          // TLEN + 1
#define NTOK  (BATCH*LSEQ)  // 65536
#define OBSD  128
#define HID   256
#define NHEAD 8
#define DHEAD 32
#define FFD   1024
#define NLAY  4
#define QKVW  (3*HID)       // 768
#define KSPLIT 8
#define KTOT   32
#define KEPS  1e-3f
#define LNEPS 1e-6f

typedef __nv_bfloat16 bf16;

// ---------------- device scratch ----------------
__device__ bf16 g_xh [(size_t)NTOK*HID];    __device__ bf16 g_xl [(size_t)NTOK*HID];
__device__ bf16 g_qkvh[(size_t)NTOK*QKVW];  __device__ bf16 g_qkvl[(size_t)NTOK*QKVW];
__device__ bf16 g_ah [(size_t)NTOK*HID];    __device__ bf16 g_al [(size_t)NTOK*HID];
__device__ bf16 g_zh [(size_t)NTOK*HID];    __device__ bf16 g_zl [(size_t)NTOK*HID];
__device__ bf16 g_fh [(size_t)NTOK*FFD];    __device__ bf16 g_fl [(size_t)NTOK*FFD];
__device__ bf16 g_insh[(size_t)(BATCH*TLEN)*OBSD];
__device__ bf16 g_insl[(size_t)(BATCH*TLEN)*OBSD];
__device__ float g_kvpart[(size_t)KTOT*BATCH*NHEAD*DHEAD*DHEAD];
__device__ float g_kspart[(size_t)KTOT*BATCH*NHEAD*DHEAD];
__device__ bf16 g_weffh[BATCH*HID*HID];
__device__ bf16 g_weffl[BATCH*HID*HID];
__device__ float g_weff2[(size_t)BATCH*HID*HID];
__device__ float g_a0[BATCH*HID];

#define WT_EMB_SZ   (HID*OBSD)
#define WT_LAYER_SZ (4*HID*HID + 2*HID*FFD)
#define WT_TOTAL    (WT_EMB_SZ + NLAY*WT_LAYER_SZ)
__device__ bf16 g_wth[WT_TOTAL];
__device__ bf16 g_wtl[WT_TOTAL];

static inline int cdiv(int a, int b) { return (a + b - 1) / b; }

// ---------------- helpers ----------------
__device__ __forceinline__ uint32_t smem_u32(const void* p) {
    uint32_t a;
    asm("{ .reg .u64 t; cvta.to.shared.u64 t, %1; cvt.u32.u64 %0, t; }" : "=r"(a) : "l"(p));
    return a;
}
__device__ __forceinline__ float hl(const bf16* H, const bf16* L, size_t i) {
    return __bfloat162float(H[i]) + __bfloat162float(L[i]);
}
__device__ __forceinline__ void sphl(float f, bf16* H, bf16* L, size_t i) {
    bf16 h = __float2bfloat16(f);
    H[i] = h;
    L[i] = __float2bfloat16(f - __bfloat162float(h));
}
__device__ __forceinline__ void unp8(const uint4& h4, const uint4& l4, float* f) {
    const __nv_bfloat162* hp = (const __nv_bfloat162*)&h4;
    const __nv_bfloat162* lp = (const __nv_bfloat162*)&l4;
    #pragma unroll
    for (int i = 0; i < 4; i++) {
        float2 hf = __bfloat1622float2(hp[i]);
        float2 lf = __bfloat1622float2(lp[i]);
        f[2*i]   = hf.x + lf.x;
        f[2*i+1] = hf.y + lf.y;
    }
}
__device__ __forceinline__ void pk8(const float* f, uint4& h4, uint4& l4) {
    uint16_t* hp = (uint16_t*)&h4;
    uint16_t* lp = (uint16_t*)&l4;
    #pragma unroll
    for (int i = 0; i < 8; i++) {
        bf16 h = __float2bfloat16(f[i]);
        bf16 l = __float2bfloat16(f[i] - __bfloat162float(h));
        hp[i] = *(uint16_t*)&h;
        lp[i] = *(uint16_t*)&l;
    }
}

#define LDSM4(r, addr)                                                     \
    asm volatile("ldmatrix.sync.aligned.m8n8.x4.shared.b16 "               \
                 "{%0,%1,%2,%3}, [%4];"                                    \
                 : "=r"((r)[0]), "=r"((r)[1]), "=r"((r)[2]), "=r"((r)[3])  \
                 : "r"(addr))

#define MMA_BF16(d, a, b0, b1)                                             \
    asm volatile("mma.sync.aligned.m16n8k16.row.col.f32.bf16.bf16.f32 "    \
                 "{%0,%1,%2,%3},{%4,%5,%6,%7},{%8,%9},{%0,%1,%2,%3};"      \
                 : "+f"((d)[0]), "+f"((d)[1]), "+f"((d)[2]), "+f"((d)[3])  \
                 : "r"((a)[0]), "r"((a)[1]), "r"((a)[2]), "r"((a)[3]),     \
                   "r"(b0), "r"(b1))

__device__ __forceinline__ void cpa16(uint32_t dst, const void* src, int sz) {
    asm volatile("cp.async.cg.shared.global [%0], [%1], 16, %2;"
                 :: "r"(dst), "l"(__cvta_generic_to_global(src)), "r"(sz));
}

// ---------------- single-launch weight conversion ----------------
__global__ void ta_wconv_all(const float* __restrict__ embW,
                             const float* __restrict__ Wq, const float* __restrict__ Wk,
                             const float* __restrict__ Wv, const float* __restrict__ Wo,
                             const float* __restrict__ W1, const float* __restrict__ W2,
                             bf16* __restrict__ hi, bf16* __restrict__ lo) {
    const int seg = blockIdx.y;
    const float* src;
    int K, N;
    size_t dst;
    if (seg == 0) {
        src = embW; K = OBSD; N = HID; dst = 0;
    } else {
        const int l = (seg - 1) / 6, m = (seg - 1) % 6;
        const size_t base = WT_EMB_SZ + (size_t)l * WT_LAYER_SZ;
        switch (m) {
            case 0: src = Wq + (size_t)l*HID*HID; K = HID; N = HID; dst = base;          break;
            case 1: src = Wk + (size_t)l*HID*HID; K = HID; N = HID; dst = base + 65536;  break;
            case 2: src = Wv + (size_t)l*HID*HID; K = HID; N = HID; dst = base + 131072; break;
            case 3: src = Wo + (size_t)l*HID*HID; K = HID; N = HID; dst = base + 196608; break;
            case 4: src = W1 + (size_t)l*HID*FFD; K = HID; N = FFD; dst = base + 262144; break;
            default:src = W2 + (size_t)l*FFD*HID; K = FFD; N = HID; dst = base + 524288; break;
        }
    }
    int i = blockIdx.x * 256 + threadIdx.x;
    if (i >= N * K) return;
    int n = i / K, k = i - n * K;
    float w = src[(size_t)k * N + n];
    bf16 h = __float2bfloat16(w);
    hi[dst + i] = h;
    lo[dst + i] = __float2bfloat16(w - __bfloat162float(h));
}

// ---------------- split ins + init hidden row ----------------
__global__ void ta_prep(const float* __restrict__ ins,
                        const float* __restrict__ hs,
                        const unsigned char* __restrict__ resets,
                        bf16* __restrict__ IH, bf16* __restrict__ IL,
                        bf16* __restrict__ XH, bf16* __restrict__ XL) {
    const int nIns = BATCH * TLEN * OBSD;
    int i = blockIdx.x * 256 + threadIdx.x;
    if (i < nIns) {
        sphl(ins[i], IH, IL, i);
    } else {
        int j = i - nIns;
        if (j < BATCH * HID) {
            int b = j >> 8, c = j & 255;
            float v = resets[b] ? 0.f : hs[b*HID + c];
            sphl(v, XH, XL, (size_t)b*LSEQ*HID + c);
        }
    }
}

// ---------------- bf16 hi/lo 3-pass MMA GEMM (3-stage, swizzled) ----------------
// flags: bit0 embRemap, bit1 qkvMode, bit2 batchedB, bit3 colOff+2 (kv-only QKV)
__global__ __launch_bounds__(256, 2)
void ta_gemm_bf16(const bf16* __restrict__ Ah, const bf16* __restrict__ Al,
                  const bf16* __restrict__ Bh, const bf16* __restrict__ Bl,
                  const float* __restrict__ bias0, const float* __restrict__ bias1,
                  const float* __restrict__ bias2,
                  bf16* __restrict__ Ch, bf16* __restrict__ Cl,
                  int M, int K, int N, int epi, int flags) {
    extern __shared__ char smem[];
    const uint32_t smu = smem_u32(smem);

    const int tid  = threadIdx.x;
    const int wid  = tid >> 5;
    const int lane = tid & 31;
    const int wr   = wid >> 2;
    const int wc   = wid & 3;
    const int rowBase = blockIdx.y * 128;
    const int colBase = (blockIdx.x + ((flags & 8) ? 2 : 0)) * 128;

    if (flags & 4) {
        const size_t boff = (size_t)(rowBase >> 12) * HID * HID;
        Bh += boff;  Bl += boff;
    }

    const int r  = tid >> 2;
    const int ch = tid & 3;
    const uint32_t stOff  = (uint32_t)(r * 64 + ((ch ^ ((r >> 1) & 3)) << 4));
    const uint32_t stOff2 = (uint32_t)((r + 64) * 64 + ((ch ^ (((r + 64) >> 1) & 3)) << 4));

    const int r15 = lane & 15;
    const int hi_ = lane >> 4;
    const int sw  = (r15 >> 1) & 3;
    const uint32_t rowB  = (uint32_t)(r15 * 64);
    const uint32_t co0   = rowB + (uint32_t)(((hi_    ) ^ sw) << 4);
    const uint32_t co1   = rowB + (uint32_t)(((2 + hi_) ^ sw) << 4);
    const uint32_t aWarp = (uint32_t)(wr * 4096);
    const uint32_t bWarp = (uint32_t)(wc * 2048);

    float acc[4][4][4] = {};

    auto load_stage = [&](int st, int kt) {
        const uint32_t sb = smu + (uint32_t)st * 32768u;
        const int kOff = kt * 32 + ch * 8;
        {
            const int grow = rowBase + r;
            const int sz = (grow < M) ? 16 : 0;
            const size_t asrc = (size_t)(sz ? grow : 0) * K + kOff;
            cpa16(sb + stOff,          Ah + asrc, sz);
            cpa16(sb + 8192u + stOff,  Al + asrc, sz);
            const size_t bsrc = (size_t)(colBase + r) * K + kOff;
            cpa16(sb + 16384u + stOff, Bh + bsrc, 16);
            cpa16(sb + 24576u + stOff, Bl + bsrc, 16);
        }
        {
            const int grow = rowBase + r + 64;
            const int sz = (grow < M) ? 16 : 0;
            const size_t asrc = (size_t)(sz ? grow : 0) * K + kOff;
            cpa16(sb + stOff2,          Ah + asrc, sz);
            cpa16(sb + 8192u + stOff2,  Al + asrc, sz);
            const size_t bsrc = (size_t)(colBase + r + 64) * K + kOff;
            cpa16(sb + 16384u + stOff2, Bh + bsrc, 16);
            cpa16(sb + 24576u + stOff2, Bl + bsrc, 16);
        }
        asm volatile("cp.async.commit_group;");
    };

    auto compute = [&](int st) {
        const uint32_t sb  = smu + (uint32_t)st * 32768u;
        const uint32_t aHB = sb + aWarp;
        const uint32_t aLB = aHB + 8192u;
        const uint32_t bHB = sb + 16384u + bWarp;
        const uint32_t bLB = bHB + 8192u;
        #pragma unroll
        for (int ks = 0; ks < 2; ks++) {
            const uint32_t co = ks ? co1 : co0;
            uint32_t bH[2][4], bL[2][4];
            LDSM4(bH[0], bHB + co);
            LDSM4(bH[1], bHB + 1024u + co);
            LDSM4(bL[0], bLB + co);
            LDSM4(bL[1], bLB + 1024u + co);
            uint32_t a[4][4];
            #pragma unroll
            for (int mi = 0; mi < 4; mi++) LDSM4(a[mi], aHB + mi * 1024u + co);
            #pragma unroll
            for (int mi = 0; mi < 4; mi++)
                #pragma unroll
                for (int nt = 0; nt < 4; nt++) {
                    MMA_BF16(acc[mi][nt], a[mi], bH[nt >> 1][nt & 1], bH[nt >> 1][(nt & 1) + 2]);
                    MMA_BF16(acc[mi][nt], a[mi], bL[nt >> 1][nt & 1], bL[nt >> 1][(nt & 1) + 2]);
                }
            #pragma unroll
            for (int mi = 0; mi < 4; mi++) LDSM4(a[mi], aLB + mi * 1024u + co);
            #pragma unroll
            for (int mi = 0; mi < 4; mi++)
                #pragma unroll
                for (int nt = 0; nt < 4; nt++)
                    MMA_BF16(acc[mi][nt], a[mi], bH[nt >> 1][nt & 1], bH[nt >> 1][(nt & 1) + 2]);
        }
    };

    const int nk = K >> 5;
    load_stage(0, 0);
    load_stage(1, 1);
    int cs = 0, ls = 2;
    for (int kt = 0; kt < nk; kt++) {
        if (kt == nk - 1) asm volatile("cp.async.wait_group 0;");
        else              asm volatile("cp.async.wait_group 1;");
        __syncthreads();
        if (kt + 2 < nk) {
            load_stage(ls, kt + 2);
            ls = (ls == 2) ? 0 : ls + 1;
        }
        compute(cs);
        cs = (cs == 2) ? 0 : cs + 1;
    }

    const bool embRemap = flags & 1;
    const bool qkvMode  = flags & 2;
    const float* bptr = bias0;
    int ep = epi;
    if (qkvMode) {
        int seg = colBase >> 8;
        bptr = (seg == 0) ? bias0 : (seg == 1) ? bias1 : bias2;
        ep = (seg < 2) ? 1 : 0;
    }
    const int t4 = lane >> 2;
    const int t2 = (lane & 3) << 1;
    #pragma unroll
    for (int mi = 0; mi < 4; mi++) {
        #pragma unroll
        for (int duo = 0; duo < 2; duo++) {
            const int row = rowBase + wr * 64 + mi * 16 + t4 + duo * 8;
            if (row >= M) continue;
            size_t orow = (size_t)row;
            if (embRemap) {
                int b = row / TLEN;
                orow = (size_t)b * LSEQ + 1 + (row - b * TLEN);
            }
            #pragma unroll
            for (int nt = 0; nt < 4; nt++) {
                const int col = colBase + wc * 32 + nt * 8 + t2;
                const int bcol = qkvMode ? (col & 255) : col;
                float c0 = acc[mi][nt][duo * 2 + 0] + bptr[bcol];
                float c1 = acc[mi][nt][duo * 2 + 1] + bptr[bcol + 1];
                if (ep == 1)      { c0 = fmaxf(c0, 0.f) + KEPS; c1 = fmaxf(c1, 0.f) + KEPS; }
                else if (ep == 2) { c0 = fmaxf(c0, 0.f);        c1 = fmaxf(c1, 0.f); }
                bf16 h0 = __float2bfloat16(c0), h1 = __float2bfloat16(c1);
                bf16 l0 = __float2bfloat16(c0 - __bfloat162float(h0));
                bf16 l1 = __float2bfloat16(c1 - __bfloat162float(h1));
                uint32_t hp = (uint32_t)*(uint16_t*)&h0 | ((uint32_t)*(uint16_t*)&h1 << 16);
                uint32_t lp = (uint32_t)*(uint16_t*)&l0 | ((uint32_t)*(uint16_t*)&l1 << 16);
                *(uint32_t*)(Ch + orow * N + col) = hp;
                *(uint32_t*)(Cl + orow * N + col) = lp;
            }
        }
    }
}

// ---------------- kv partials: register-tiled (4x4 per thread) ----------------
__global__ void ta_kv_reduce(const bf16* __restrict__ QKVh, const bf16* __restrict__ QKVl,
                             float* __restrict__ KVp, float* __restrict__ KSp) {
    const int s = blockIdx.x, h = blockIdx.y, b = blockIdx.z;
    const int tid = threadIdx.x;

    __shared__ float kp[32][36];
    __shared__ float vv[32][36];

    const size_t rowBase = (size_t)b * LSEQ + (size_t)s * (LSEQ / KSPLIT);

    const int row_ = tid >> 3;
    const int part = tid & 7;
    const int isV  = part >> 2;
    const int cseg = (part & 3) * 8;
    float* stDst = (isV ? &vv[row_][cseg] : &kp[row_][cseg]);

    const int tsub = tid >> 6;
    const int t64  = tid & 63;
    const int tm4  = (t64 >> 3) << 2;
    const int td4  = (t64 & 7) << 2;
    const bool ksaOwner = ((t64 & 7) == 0);

    float acc[4][4] = {};
    float ksa[4] = {0.f, 0.f, 0.f, 0.f};

    for (int c0 = 0; c0 < LSEQ / KSPLIT; c0 += 32) {
        {
            const size_t g = (rowBase + c0 + row_) * QKVW
                           + (isV ? 2*HID : HID) + h * DHEAD + cseg;
            uint4 h4 = *(const uint4*)(QKVh + g);
            uint4 l4 = *(const uint4*)(QKVl + g);
            float f[8];
            unp8(h4, l4, f);
            *(float4*)(stDst)     = make_float4(f[0], f[1], f[2], f[3]);
            *(float4*)(stDst + 4) = make_float4(f[4], f[5], f[6], f[7]);
        }
        __syncthreads();
        #pragma unroll
        for (int q = 0; q < 8; q++) {
            const int l = tsub * 8 + q;
            float4 kq = *(const float4*)&kp[l][tm4];
            float4 vq = *(const float4*)&vv[l][td4];
            float km[4] = {kq.x, kq.y, kq.z, kq.w};
            float vd[4] = {vq.x, vq.y, vq.z, vq.w};
            #pragma unroll
            for (int i = 0; i < 4; i++)
                #pragma unroll
                for (int j = 0; j < 4; j++)
                    acc[i][j] += km[i] * vd[j];
            if (ksaOwner) {
                #pragma unroll
                for (int i = 0; i < 4; i++) ksa[i] += km[i];
            }
        }
        __syncthreads();
    }

    const int bh = b * NHEAD + h;
    const size_t slot = (size_t)(s * 4 + tsub) * BATCH * NHEAD + bh;
    #pragma unroll
    for (int i = 0; i < 4; i++)
        *(float4*)&KVp[slot * 1024 + (tm4 + i) * 32 + td4] =
            make_float4(acc[i][0], acc[i][1], acc[i][2], acc[i][3]);
    if (ksaOwner)
        *(float4*)&KSp[slot * 32 + tm4] = make_float4(ksa[0], ksa[1], ksa[2], ksa[3]);
}

// ---------------- WeffT = blockdiag(kv) @ Wo ----------------
__global__ void ta_weff(const float* __restrict__ KVp, const float* __restrict__ Wo,
                        bf16* __restrict__ WH, bf16* __restrict__ WL,
                        float* __restrict__ W2f) {
    const int h = blockIdx.x, b = blockIdx.y;
    const int tid = threadIdx.x;
    const int bh = b * NHEAD + h;
    __shared__ float kvs[DHEAD*DHEAD];
    for (int i = tid; i < DHEAD*DHEAD; i += 256) {
        float v = 0.f;
        #pragma unroll
        for (int s = 0; s < KTOT; s++)
            v += KVp[((size_t)s * BATCH*NHEAD + bh) * 1024 + i];
        kvs[i] = v;
    }
    __syncthreads();

    float wcol[DHEAD];
    #pragma unroll
    for (int d = 0; d < DHEAD; d++)
        wcol[d] = Wo[((size_t)h*DHEAD + d)*HID + tid];

    for (int m = 0; m < DHEAD; m++) {
        const float4* k4 = (const float4*)&kvs[m*DHEAD];
        float a0 = 0.f;
        #pragma unroll
        for (int q = 0; q < 8; q++) {
            float4 kk = k4[q];
            a0 += kk.x*wcol[4*q] + kk.y*wcol[4*q+1] + kk.z*wcol[4*q+2] + kk.w*wcol[4*q+3];
        }
        size_t idx = ((size_t)b*HID + tid)*HID + h*DHEAD + m;
        bf16 hh = __float2bfloat16(a0);
        WH[idx] = hh;
        WL[idx] = __float2bfloat16(a0 - __bfloat162float(hh));
        W2f[((size_t)b*HID + h*DHEAD + m)*HID + tid] = a0;
    }
}

// ---------------- qp' = qp / (qp . ksum) ----------------
__global__ void ta_qpscale(const bf16* __restrict__ QKVh, const bf16* __restrict__ QKVl,
                           const float* __restrict__ KSp,
                           bf16* __restrict__ AH, bf16* __restrict__ AL) {
    __shared__ float kss[HID];
    const int b = blockIdx.y;
    const int tokBase = blockIdx.x * 32;
    const int tid = threadIdx.x;
    {
        const int h2 = tid >> 5, m = tid & 31;
        float v = 0.f;
        #pragma unroll
        for (int s = 0; s < KTOT; s++)
            v += KSp[((size_t)s * BATCH*NHEAD + b*NHEAD + h2) * 32 + m];
        kss[tid] = v;
    }
    __syncthreads();

    const int tok = tokBase + (tid >> 3);
    const int h   = tid & 7;
    const size_t qrow = ((size_t)b * LSEQ + tok) * QKVW + h * DHEAD;
    const size_t arow = ((size_t)b * LSEQ + tok) * HID  + h * DHEAD;

    float qv[DHEAD];
    #pragma unroll
    for (int g = 0; g < 4; g++) {
        uint4 h4 = *(const uint4*)(QKVh + qrow + g*8);
        uint4 l4 = *(const uint4*)(QKVl + qrow + g*8);
        unp8(h4, l4, qv + g*8);
    }
    float den = 0.f;
    #pragma unroll
    for (int m = 0; m < DHEAD; m++) den += qv[m] * kss[h*DHEAD + m];
    const float inv = 1.f / den;
    #pragma unroll
    for (int m = 0; m < DHEAD; m++) qv[m] *= inv;
    #pragma unroll
    for (int g = 0; g < 4; g++) {
        uint4 h4, l4;
        pk8(qv + g*8, h4, l4);
        *(uint4*)(AH + arow + g*8) = h4;
        *(uint4*)(AL + arow + g*8) = l4;
    }
}

// ---------------- X = LN(2*Z)*scale + bias ----------------
__global__ void ta_ln2(const bf16* __restrict__ ZH, const bf16* __restrict__ ZL,
                       const float* __restrict__ sc, const float* __restrict__ bi,
                       bf16* __restrict__ XH, bf16* __restrict__ XL) {
    const int row  = blockIdx.x * 8 + threadIdx.y;
    const int lane = threadIdx.x;
    const size_t base = (size_t)row * HID + lane * 8;

    float v[8];
    {
        uint4 h4 = *(const uint4*)(ZH + base);
        uint4 l4 = *(const uint4*)(ZL + base);
        unp8(h4, l4, v);
    }
    float sum = 0.f;
    #pragma unroll
    for (int j = 0; j < 8; j++) { v[j] *= 2.f; sum += v[j]; }
    #pragma unroll
    for (int o = 16; o; o >>= 1) sum += __shfl_xor_sync(0xffffffffu, sum, o);
    const float mean = sum * (1.f / HID);

    float vs = 0.f;
    #pragma unroll
    for (int j = 0; j < 8; j++) { float d = v[j] - mean; vs += d * d; }
    #pragma unroll
    for (int o = 16; o; o >>= 1) vs += __shfl_xor_sync(0xffffffffu, vs, o);
    const float rr = rsqrtf(vs * (1.f / HID) + LNEPS);

    float o8[8];
    #pragma unroll
    for (int j = 0; j < 8; j++) {
        int c = lane * 8 + j;
        o8[j] = (v[j] - mean) * rr * sc[c] + bi[c];
    }
    uint4 h4, l4;
    pk8(o8, h4, l4);
    *(uint4*)(XH + base) = h4;
    *(uint4*)(XL + base) = l4;
}

// ---------------- last layer token-0 kernels ----------------
__global__ void ta_lastq(const bf16* __restrict__ XH, const bf16* __restrict__ XL,
                         const float* __restrict__ Wq3, const float* __restrict__ bq3,
                         const float* __restrict__ KSp, float* __restrict__ A0) {
    const int b = blockIdx.x, c = threadIdx.x;
    __shared__ float xs[HID], qps[HID], kss[HID];
    xs[c] = hl(XH, XL, (size_t)b*LSEQ*HID + c);
    {
        const int h2 = c >> 5, m = c & 31;
        float v = 0.f;
        #pragma unroll
        for (int s = 0; s < KTOT; s++)
            v += KSp[((size_t)s * BATCH*NHEAD + b*NHEAD + h2) * 32 + m];
        kss[c] = v;
    }
    __syncthreads();
    float q = bq3[c];
    #pragma unroll 8
    for (int d = 0; d < HID; d++) q += xs[d] * Wq3[(size_t)d*HID + c];
    float qp = fmaxf(q, 0.f) + KEPS;
    qps[c] = qp;
    __syncthreads();
    const int h = c >> 5;
    float den = 0.f;
    #pragma unroll
    for (int m = 0; m < DHEAD; m++) den += qps[h*DHEAD + m] * kss[h*DHEAD + m];
    A0[b*HID + c] = qp / den;
}

__global__ void ta_lastmile(const float* __restrict__ A0, const float* __restrict__ W2f,
                            const float* __restrict__ bo3,
                            const float* __restrict__ ln1s3, const float* __restrict__ ln1b3,
                            const float* __restrict__ W1_3, const float* __restrict__ b1_3,
                            const float* __restrict__ W2_3, const float* __restrict__ b2_3,
                            const float* __restrict__ ln2s3, const float* __restrict__ ln2b3,
                            const float* __restrict__ qpW, const float* __restrict__ qpb,
                            float* __restrict__ out) {
    const int b = blockIdx.x, c = threadIdx.x;
    const int wid = c >> 5, lane = c & 31;
    __shared__ float a0[HID], x1[HID], f[FFD], xo[HID], sred[16];

    a0[c] = A0[b*HID + c];
    __syncthreads();

    float o = bo3[c];
    const float* w = W2f + (size_t)b*HID*HID;
    #pragma unroll 8
    for (int d = 0; d < HID; d++) o += a0[d] * w[(size_t)d*HID + c];
    float v = 2.f * o;

    {
        float s = v, q = v * v;
        #pragma unroll
        for (int off = 16; off; off >>= 1) {
            s += __shfl_xor_sync(0xffffffffu, s, off);
            q += __shfl_xor_sync(0xffffffffu, q, off);
        }
        if (lane == 0) { sred[wid] = s; sred[8 + wid] = q; }
        __syncthreads();
        float ts = 0.f, tq = 0.f;
        #pragma unroll
        for (int i = 0; i < 8; i++) { ts += sred[i]; tq += sred[8 + i]; }
        const float mean = ts * (1.f / HID);
        const float var  = tq * (1.f / HID) - mean * mean;
        const float rr   = rsqrtf(var + LNEPS);
        x1[c] = (v - mean) * rr * ln1s3[c] + ln1b3[c];
        __syncthreads();
    }

    #pragma unroll
    for (int jj = 0; jj < 4; jj++) {
        const int j = c + jj * 256;
        float s = b1_3[j];
        #pragma unroll 8
        for (int d = 0; d < HID; d++) s += x1[d] * W1_3[(size_t)d*FFD + j];
        f[j] = fmaxf(s, 0.f);
    }
    __syncthreads();

    float z = b2_3[c];
    #pragma unroll 8
    for (int j = 0; j < FFD; j++) z += f[j] * W2_3[(size_t)j*HID + c];
    float v2 = 2.f * z;

    {
        float s = v2, q = v2 * v2;
        #pragma unroll
        for (int off = 16; off; off >>= 1) {
            s += __shfl_xor_sync(0xffffffffu, s, off);
            q += __shfl_xor_sync(0xffffffffu, q, off);
        }
        __syncthreads();
        if (lane == 0) { sred[wid] = s; sred[8 + wid] = q; }
        __syncthreads();
        float ts = 0.f, tq = 0.f;
        #pragma unroll
        for (int i = 0; i < 8; i++) { ts += sred[i]; tq += sred[8 + i]; }
        const float mean = ts * (1.f / HID);
        const float var  = tq * (1.f / HID) - mean * mean;
        const float rr   = rsqrtf(var + LNEPS);
        xo[c] = (v2 - mean) * rr * ln2s3[c] + ln2b3[c];
    }
    out[b*HID + c] = xo[c];
    __syncthreads();

    if (c < 32) {
        float s = qpb[c];
        #pragma unroll 8
        for (int d = 0; d < HID; d++) s += xo[d] * qpW[d*32 + c];
        out[BATCH*HID + b*32 + c] = s;
    }
}

// ---------------- launcher ----------------
extern "C" void kernel_launch(void* const* d_in, const int* in_sizes, int n_in,
                              void* d_out, int out_size) {
    const float* hidden = (const float*)d_in[0];
    const float* ins    = (const float*)d_in[1];
    const unsigned char* resets = (const unsigned char*)d_in[2];
    const float* embW = (const float*)d_in[3];
    const float* embb = (const float*)d_in[4];
    const float* Wq = (const float*)d_in[5];
    const float* bq = (const float*)d_in[6];
    const float* Wk = (const float*)d_in[7];
    const float* bk = (const float*)d_in[8];
    const float* Wv = (const float*)d_in[9];
    const float* bv = (const float*)d_in[10];
    const float* Wo = (const float*)d_in[11];
    const float* bo = (const float*)d_in[12];
    const float* ln1s = (const float*)d_in[13];
    const float* ln1b = (const float*)d_in[14];
    const float* W1 = (const float*)d_in[15];
    const float* b1 = (const float*)d_in[16];
    const float* W2 = (const float*)d_in[17];
    const float* b2 = (const float*)d_in[18];
    const float* ln2s = (const float*)d_in[19];
    const float* ln2b = (const float*)d_in[20];
    const float* qpW = (const float*)d_in[21];
    const float* qpb = (const float*)d_in[22];

    bf16 *xh,*xl,*qkvh,*qkvl,*ah,*al,*zh,*zl,*fh,*fl,*insh,*insl,*wth,*wtl,*weh,*wel;
    float *kvp, *ksp, *w2f, *a0;
    cudaGetSymbolAddress((void**)&xh,   g_xh);   cudaGetSymbolAddress((void**)&xl,   g_xl);
    cudaGetSymbolAddress((void**)&qkvh, g_qkvh); cudaGetSymbolAddress((void**)&qkvl, g_qkvl);
    cudaGetSymbolAddress((void**)&ah,   g_ah);   cudaGetSymbolAddress((void**)&al,   g_al);
    cudaGetSymbolAddress((void**)&zh,   g_zh);   cudaGetSymbolAddress((void**)&zl,   g_zl);
    cudaGetSymbolAddress((void**)&fh,   g_fh);   cudaGetSymbolAddress((void**)&fl,   g_fl);
    cudaGetSymbolAddress((void**)&insh, g_insh); cudaGetSymbolAddress((void**)&insl, g_insl);
    cudaGetSymbolAddress((void**)&wth,  g_wth);  cudaGetSymbolAddress((void**)&wtl,  g_wtl);
    cudaGetSymbolAddress((void**)&weh,  g_weffh);cudaGetSymbolAddress((void**)&wel,  g_weffl);
    cudaGetSymbolAddress((void**)&kvp,  g_kvpart); cudaGetSymbolAddress((void**)&ksp, g_kspart);
    cudaGetSymbolAddress((void**)&w2f,  g_weff2);  cudaGetSymbolAddress((void**)&a0,  g_a0);

    const int GEMM_SMEM = 98304;
    cudaFuncSetAttribute(ta_gemm_bf16, cudaFuncAttributeMaxDynamicSharedMemorySize, GEMM_SMEM);

    ta_wconv_all<<<dim3(1024, 25), 256>>>(embW, Wq, Wk, Wv, Wo, W1, W2, wth, wtl);
    {
        int n = BATCH*TLEN*OBSD + BATCH*HID;
        ta_prep<<<cdiv(n,256), 256>>>(ins, hidden, resets, insh, insl, xh, xl);
    }
    {
        int M = BATCH * TLEN;
        ta_gemm_bf16<<<dim3(HID/128, cdiv(M,128)), 256, GEMM_SMEM>>>(
            insh, insl, wth, wtl, embb, embb, embb, xh, xl, M, OBSD, HID, 0, 1);
    }

    const dim3 gqkv(QKVW/128, NTOK/128);  // (6, 512)
    const dim3 gkv (4,        NTOK/128);  // kv-only, col tiles 2..5
    const dim3 g256(HID/128,  NTOK/128);  // (2, 512)
    const dim3 gff (FFD/128,  NTOK/128);  // (8, 512)

    for (int l = 0; l < NLAY; l++) {
        const bool last = (l == NLAY - 1);
        size_t base = WT_EMB_SZ + (size_t)l * WT_LAYER_SZ;
        const bf16 *qkvwh = wth + base,          *qkvwl = wtl + base;
        const bf16 *w1h   = wth + base + 262144, *w1l   = wtl + base + 262144;
        const bf16 *w2h   = wth + base + 524288, *w2l   = wtl + base + 524288;

        if (!last) {
            ta_gemm_bf16<<<gqkv, 256, GEMM_SMEM>>>(xh, xl, qkvwh, qkvwl,
                                                   bq + l*HID, bk + l*HID, bv + l*HID,
                                                   qkvh, qkvl, NTOK, HID, QKVW, 0, 2);
        } else {
            ta_gemm_bf16<<<gkv, 256, GEMM_SMEM>>>(xh, xl, qkvwh, qkvwl,
                                                  bq + l*HID, bk + l*HID, bv + l*HID,
                                                  qkvh, qkvl, NTOK, HID, QKVW, 0, 2 | 8);
        }
        ta_kv_reduce<<<dim3(KSPLIT, NHEAD, BATCH), 256>>>(qkvh, qkvl, kvp, ksp);
        ta_weff<<<dim3(NHEAD, BATCH), 256>>>(kvp, Wo + (size_t)l*HID*HID, weh, wel, w2f);

        if (!last) {
            ta_qpscale<<<dim3(LSEQ/32, BATCH), 256>>>(qkvh, qkvl, ksp, ah, al);
            ta_gemm_bf16<<<g256, 256, GEMM_SMEM>>>(ah, al, weh, wel,
                                                   bo + l*HID, bo + l*HID, bo + l*HID,
                                                   zh, zl, NTOK, HID, HID, 0, 4);
            ta_ln2<<<NTOK/8, dim3(32,8)>>>(zh, zl, ln1s + l*HID, ln1b + l*HID, xh, xl);

            ta_gemm_bf16<<<gff, 256, GEMM_SMEM>>>(xh, xl, w1h, w1l,
                                                  b1 + l*FFD, b1 + l*FFD, b1 + l*FFD,
                                                  fh, fl, NTOK, HID, FFD, 2, 0);
            ta_gemm_bf16<<<g256, 256, GEMM_SMEM>>>(fh, fl, w2h, w2l,
                                                   b2 + l*HID, b2 + l*HID, b2 + l*HID,
                                                   zh, zl, NTOK, FFD, HID, 0, 0);
            ta_ln2<<<NTOK/8, dim3(32,8)>>>(zh, zl, ln2s + l*HID, ln2b + l*HID, xh, xl);
        } else {
            ta_lastq<<<BATCH, 256>>>(xh, xl, Wq + (size_t)l*HID*HID, bq + l*HID, ksp, a0);
            ta_lastmile<<<BATCH, 256>>>(a0, w2f, bo + l*HID,
                                        ln1s + l*HID, ln1b + l*HID,
                                        W1 + (size_t)l*HID*FFD, b1 + l*FFD,
                                        W2 + (size_t)l*FFD*HID, b2 + l*HID,
                                        ln2s + l*HID, ln2b + l*HID,
                                        qpW, qpb, (float*)d_out);
        }
    }
}

// round 16
// speedup vs baseline: 1.2555x; 1.0049x over previous
#include <cuda_runtime.h>
#include <cuda_bf16.h>
#include <cstdint>

// ---------------- problem constants ----------------
#define BATCH 16
#define TLEN  4095
#define LSEQ  4096          // TLEN + 1
#define NTOK  (BATCH*LSEQ)  // 65536
#define OBSD  128
#define HID   256
#define NHEAD 8
#define DHEAD 32
#define FFD   1024
#define NLAY  4
#define QKVW  (3*HID)       // 768
#define KSPLIT 8
#define KTOT   32
#define KEPS  1e-3f
#define LNEPS 1e-6f

typedef __nv_bfloat16 bf16;

// ---------------- device scratch ----------------
__device__ bf16 g_xh [(size_t)NTOK*HID];    __device__ bf16 g_xl [(size_t)NTOK*HID];
__device__ bf16 g_qkvh[(size_t)NTOK*QKVW];  __device__ bf16 g_qkvl[(size_t)NTOK*QKVW];
__device__ bf16 g_ah [(size_t)NTOK*HID];    __device__ bf16 g_al [(size_t)NTOK*HID];
__device__ bf16 g_zh [(size_t)NTOK*HID];    __device__ bf16 g_zl [(size_t)NTOK*HID];
__device__ bf16 g_fh [(size_t)NTOK*FFD];    __device__ bf16 g_fl [(size_t)NTOK*FFD];
__device__ bf16 g_insh[(size_t)(BATCH*TLEN)*OBSD];
__device__ bf16 g_insl[(size_t)(BATCH*TLEN)*OBSD];
__device__ float g_kvpart[(size_t)KTOT*BATCH*NHEAD*DHEAD*DHEAD];
__device__ float g_kspart[(size_t)KTOT*BATCH*NHEAD*DHEAD];
__device__ bf16 g_weffh[BATCH*HID*HID];
__device__ bf16 g_weffl[BATCH*HID*HID];
__device__ float g_weff2[(size_t)BATCH*HID*HID];
__device__ float g_a0[BATCH*HID];
__device__ float2 g_stats[2*NTOK];          // per-row (sum c, sum c^2) partials, 2 col-blocks
// S/C vectors: FFN1 l=0..2 at l*1024 ; QKV l=1..3 at 3072+(l-1)*768
#define SNC_TOTAL (3*FFD + 3*QKVW)          // 5376
__device__ float g_sv[SNC_TOTAL];
__device__ float g_cv[SNC_TOTAL];

#define WT_EMB_SZ   (HID*OBSD)
#define WT_LAYER_SZ (4*HID*HID + 2*HID*FFD)
#define WT_TOTAL    (WT_EMB_SZ + NLAY*WT_LAYER_SZ)
__device__ bf16 g_wth[WT_TOTAL];
__device__ bf16 g_wtl[WT_TOTAL];

static inline int cdiv(int a, int b) { return (a + b - 1) / b; }

// ---------------- helpers ----------------
__device__ __forceinline__ uint32_t smem_u32(const void* p) {
    uint32_t a;
    asm("{ .reg .u64 t; cvta.to.shared.u64 t, %1; cvt.u32.u64 %0, t; }" : "=r"(a) : "l"(p));
    return a;
}
__device__ __forceinline__ float hl(const bf16* H, const bf16* L, size_t i) {
    return __bfloat162float(H[i]) + __bfloat162float(L[i]);
}
__device__ __forceinline__ void sphl(float f, bf16* H, bf16* L, size_t i) {
    bf16 h = __float2bfloat16(f);
    H[i] = h;
    L[i] = __float2bfloat16(f - __bfloat162float(h));
}
__device__ __forceinline__ void unp8(const uint4& h4, const uint4& l4, float* f) {
    const __nv_bfloat162* hp = (const __nv_bfloat162*)&h4;
    const __nv_bfloat162* lp = (const __nv_bfloat162*)&l4;
    #pragma unroll
    for (int i = 0; i < 4; i++) {
        float2 hf = __bfloat1622float2(hp[i]);
        float2 lf = __bfloat1622float2(lp[i]);
        f[2*i]   = hf.x + lf.x;
        f[2*i+1] = hf.y + lf.y;
    }
}
__device__ __forceinline__ void pk8(const float* f, uint4& h4, uint4& l4) {
    uint16_t* hp = (uint16_t*)&h4;
    uint16_t* lp = (uint16_t*)&l4;
    #pragma unroll
    for (int i = 0; i < 8; i++) {
        bf16 h = __float2bfloat16(f[i]);
        bf16 l = __float2bfloat16(f[i] - __bfloat162float(h));
        hp[i] = *(uint16_t*)&h;
        lp[i] = *(uint16_t*)&l;
    }
}

#define LDSM4(r, addr)                                                     \
    asm volatile("ldmatrix.sync.aligned.m8n8.x4.shared.b16 "               \
                 "{%0,%1,%2,%3}, [%4];"                                    \
                 : "=r"((r)[0]), "=r"((r)[1]), "=r"((r)[2]), "=r"((r)[3])  \
                 : "r"(addr))

#define MMA_BF16(d, a, b0, b1)                                             \
    asm volatile("mma.sync.aligned.m16n8k16.row.col.f32.bf16.bf16.f32 "    \
                 "{%0,%1,%2,%3},{%4,%5,%6,%7},{%8,%9},{%0,%1,%2,%3};"      \
                 : "+f"((d)[0]), "+f"((d)[1]), "+f"((d)[2]), "+f"((d)[3])  \
                 : "r"((a)[0]), "r"((a)[1]), "r"((a)[2]), "r"((a)[3]),     \
                   "r"(b0), "r"(b1))

__device__ __forceinline__ void cpa16(uint32_t dst, const void* src, int sz) {
    asm volatile("cp.async.cg.shared.global [%0], [%1], 16, %2;"
                 :: "r"(dst), "l"(__cvta_generic_to_global(src)), "r"(sz));
}

// ---------------- weight conversion (transpose + hi/lo; LN-scale fold) --------
// W' = diag(sc)*W for: W1 (l<3, sc=ln1s_l), Wq/Wk/Wv (l>=1, sc=ln2s_{l-1}).
__global__ void ta_wconv_all(const float* __restrict__ embW,
                             const float* __restrict__ Wq, const float* __restrict__ Wk,
                             const float* __restrict__ Wv, const float* __restrict__ Wo,
                             const float* __restrict__ W1, const float* __restrict__ W2,
                             const float* __restrict__ ln1s, const float* __restrict__ ln2s,
                             bf16* __restrict__ hi, bf16* __restrict__ lo) {
    const int seg = blockIdx.y;
    const float* src;
    const float* scv = nullptr;
    int K, N;
    size_t dst;
    if (seg == 0) {
        src = embW; K = OBSD; N = HID; dst = 0;
    } else {
        const int l = (seg - 1) / 6, m = (seg - 1) % 6;
        const size_t base = WT_EMB_SZ + (size_t)l * WT_LAYER_SZ;
        switch (m) {
            case 0: src = Wq + (size_t)l*HID*HID; K = HID; N = HID; dst = base;
                    if (l >= 1) scv = ln2s + (l-1)*HID; break;
            case 1: src = Wk + (size_t)l*HID*HID; K = HID; N = HID; dst = base + 65536;
                    if (l >= 1) scv = ln2s + (l-1)*HID; break;
            case 2: src = Wv + (size_t)l*HID*HID; K = HID; N = HID; dst = base + 131072;
                    if (l >= 1) scv = ln2s + (l-1)*HID; break;
            case 3: src = Wo + (size_t)l*HID*HID; K = HID; N = HID; dst = base + 196608; break;
            case 4: src = W1 + (size_t)l*HID*FFD; K = HID; N = FFD; dst = base + 262144;
                    if (l < 3) scv = ln1s + l*HID; break;
            default:src = W2 + (size_t)l*FFD*HID; K = FFD; N = HID; dst = base + 524288; break;
        }
    }
    int i = blockIdx.x * 256 + threadIdx.x;
    if (i >= N * K) return;
    int n = i / K, k = i - n * K;
    float w = src[(size_t)k * N + n];
    if (scv) w *= scv[k];
    bf16 h = __float2bfloat16(w);
    hi[dst + i] = h;
    lo[dst + i] = __float2bfloat16(w - __bfloat162float(h));
}

// ---------------- S = sc^T W, C = bi^T W vectors ----------------
__global__ void ta_snc(const float* __restrict__ Wq, const float* __restrict__ Wk,
                       const float* __restrict__ Wv, const float* __restrict__ W1,
                       const float* __restrict__ ln1s, const float* __restrict__ ln1b,
                       const float* __restrict__ ln2s, const float* __restrict__ ln2b,
                       float* __restrict__ SV, float* __restrict__ CV) {
    int idx = blockIdx.x * 256 + threadIdx.x;
    if (idx >= SNC_TOTAL) return;
    float S = 0.f, C = 0.f;
    if (idx < 3*FFD) {
        const int l = idx / FFD, n = idx % FFD;
        const float* W = W1 + (size_t)l*HID*FFD;
        const float* s = ln1s + l*HID;
        const float* b = ln1b + l*HID;
        for (int k = 0; k < HID; k++) {
            float w = W[(size_t)k*FFD + n];
            S += s[k]*w; C += b[k]*w;
        }
    } else {
        const int j = idx - 3*FFD;
        const int l = j / QKVW + 1, n = j % QKVW;
        const int sg = n >> 8, nn = n & 255;
        const float* W = (sg == 0 ? Wq : sg == 1 ? Wk : Wv) + (size_t)l*HID*HID;
        const float* s = ln2s + (l-1)*HID;
        const float* b = ln2b + (l-1)*HID;
        for (int k = 0; k < HID; k++) {
            float w = W[(size_t)k*HID + nn];
            S += s[k]*w; C += b[k]*w;
        }
    }
    SV[idx] = S; CV[idx] = C;
}

// ---------------- split ins + init hidden row ----------------
__global__ void ta_prep(const float* __restrict__ ins,
                        const float* __restrict__ hs,
                        const unsigned char* __restrict__ resets,
                        bf16* __restrict__ IH, bf16* __restrict__ IL,
                        bf16* __restrict__ XH, bf16* __restrict__ XL) {
    const int nIns = BATCH * TLEN * OBSD;
    int i = blockIdx.x * 256 + threadIdx.x;
    if (i < nIns) {
        sphl(ins[i], IH, IL, i);
    } else {
        int j = i - nIns;
        if (j < BATCH * HID) {
            int b = j >> 8, c = j & 255;
            float v = resets[b] ? 0.f : hs[b*HID + c];
            sphl(v, XH, XL, (size_t)b*LSEQ*HID + c);
        }
    }
}

// ---------------- bf16 hi/lo 3-pass MMA GEMM (3-stage, swizzled) ----------------
// flags: bit0 embRemap, bit1 qkvMode, bit2 batchedB, bit3 colOff+2 (kv-only),
//        bit5 statsOut (write per-row sum/sumsq partials),
//        bit6 lnIn (A is pre-LN z; apply affine LN fold with Svec/Cvec + stats)
__global__ __launch_bounds__(256, 2)
void ta_gemm_bf16(const bf16* __restrict__ Ah, const bf16* __restrict__ Al,
                  const bf16* __restrict__ Bh, const bf16* __restrict__ Bl,
                  const float* __restrict__ bias0, const float* __restrict__ bias1,
                  const float* __restrict__ bias2,
                  const float* __restrict__ Svec, const float* __restrict__ Cvec,
                  float2* __restrict__ stats,
                  bf16* __restrict__ Ch, bf16* __restrict__ Cl,
                  int M, int K, int N, int epi, int flags) {
    extern __shared__ char smem[];
    const uint32_t smu = smem_u32(smem);

    const int tid  = threadIdx.x;
    const int wid  = tid >> 5;
    const int lane = tid & 31;
    const int wr   = wid >> 2;
    const int wc   = wid & 3;
    const int rowBase = blockIdx.y * 128;
    const int colBase = (blockIdx.x + ((flags & 8) ? 2 : 0)) * 128;

    if (flags & 4) {
        const size_t boff = (size_t)(rowBase >> 12) * HID * HID;
        Bh += boff;  Bl += boff;
    }

    const int r  = tid >> 2;
    const int ch = tid & 3;
    const uint32_t stOff  = (uint32_t)(r * 64 + ((ch ^ ((r >> 1) & 3)) << 4));
    const uint32_t stOff2 = (uint32_t)((r + 64) * 64 + ((ch ^ (((r + 64) >> 1) & 3)) << 4));

    const int r15 = lane & 15;
    const int hi_ = lane >> 4;
    const int sw  = (r15 >> 1) & 3;
    const uint32_t rowB  = (uint32_t)(r15 * 64);
    const uint32_t co0   = rowB + (uint32_t)(((hi_    ) ^ sw) << 4);
    const uint32_t co1   = rowB + (uint32_t)(((2 + hi_) ^ sw) << 4);
    const uint32_t aWarp = (uint32_t)(wr * 4096);
    const uint32_t bWarp = (uint32_t)(wc * 2048);

    float acc[4][4][4] = {};

    auto load_stage = [&](int st, int kt) {
        const uint32_t sb = smu + (uint32_t)st * 32768u;
        const int kOff = kt * 32 + ch * 8;
        {
            const int grow = rowBase + r;
            const int sz = (grow < M) ? 16 : 0;
            const size_t asrc = (size_t)(sz ? grow : 0) * K + kOff;
            cpa16(sb + stOff,          Ah + asrc, sz);
            cpa16(sb + 8192u + stOff,  Al + asrc, sz);
            const size_t bsrc = (size_t)(colBase + r) * K + kOff;
            cpa16(sb + 16384u + stOff, Bh + bsrc, 16);
            cpa16(sb + 24576u + stOff, Bl + bsrc, 16);
        }
        {
            const int grow = rowBase + r + 64;
            const int sz = (grow < M) ? 16 : 0;
            const size_t asrc = (size_t)(sz ? grow : 0) * K + kOff;
            cpa16(sb + stOff2,          Ah + asrc, sz);
            cpa16(sb + 8192u + stOff2,  Al + asrc, sz);
            const size_t bsrc = (size_t)(colBase + r + 64) * K + kOff;
            cpa16(sb + 16384u + stOff2, Bh + bsrc, 16);
            cpa16(sb + 24576u + stOff2, Bl + bsrc, 16);
        }
        asm volatile("cp.async.commit_group;");
    };

    auto compute = [&](int st) {
        const uint32_t sb  = smu + (uint32_t)st * 32768u;
        const uint32_t aHB = sb + aWarp;
        const uint32_t aLB = aHB + 8192u;
        const uint32_t bHB = sb + 16384u + bWarp;
        const uint32_t bLB = bHB + 8192u;
        #pragma unroll
        for (int ks = 0; ks < 2; ks++) {
            const uint32_t co = ks ? co1 : co0;
            uint32_t bH[2][4], bL[2][4];
            LDSM4(bH[0], bHB + co);
            LDSM4(bH[1], bHB + 1024u + co);
            LDSM4(bL[0], bLB + co);
            LDSM4(bL[1], bLB + 1024u + co);
            uint32_t a[4][4];
            #pragma unroll
            for (int mi = 0; mi < 4; mi++) LDSM4(a[mi], aHB + mi * 1024u + co);
            #pragma unroll
            for (int mi = 0; mi < 4; mi++)
                #pragma unroll
                for (int nt = 0; nt < 4; nt++) {
                    MMA_BF16(acc[mi][nt], a[mi], bH[nt >> 1][nt & 1], bH[nt >> 1][(nt & 1) + 2]);
                    MMA_BF16(acc[mi][nt], a[mi], bL[nt >> 1][nt & 1], bL[nt >> 1][(nt & 1) + 2]);
                }
            #pragma unroll
            for (int mi = 0; mi < 4; mi++) LDSM4(a[mi], aLB + mi * 1024u + co);
            #pragma unroll
            for (int mi = 0; mi < 4; mi++)
                #pragma unroll
                for (int nt = 0; nt < 4; nt++)
                    MMA_BF16(acc[mi][nt], a[mi], bH[nt >> 1][nt & 1], bH[nt >> 1][(nt & 1) + 2]);
        }
    };

    const int nk = K >> 5;
    load_stage(0, 0);
    load_stage(1, 1);
    int cs = 0, ls = 2;
    for (int kt = 0; kt < nk; kt++) {
        if (kt == nk - 1) asm volatile("cp.async.wait_group 0;");
        else              asm volatile("cp.async.wait_group 1;");
        __syncthreads();
        if (kt + 2 < nk) {
            load_stage(ls, kt + 2);
            ls = (ls == 2) ? 0 : ls + 1;
        }
        compute(cs);
        cs = (cs == 2) ? 0 : cs + 1;
    }

    // ---- epilogue
    const bool embRemap = flags & 1;
    const bool qkvMode  = flags & 2;
    const bool statsOut = flags & 32;
    const bool lnIn     = flags & 64;
    float* sst = (float*)smem;     // 128 rows x 8 floats (4 wc x {sum,sq}) = 4KB
    if (statsOut) __syncthreads(); // stage smem no longer needed

    const float* bptr = bias0;
    int ep = epi;
    if (qkvMode) {
        int seg = colBase >> 8;
        bptr = (seg == 0) ? bias0 : (seg == 1) ? bias1 : bias2;
        ep = (seg < 2) ? 1 : 0;
    }
    const int t4 = lane >> 2;
    const int t2 = (lane & 3) << 1;
    #pragma unroll
    for (int mi = 0; mi < 4; mi++) {
        #pragma unroll
        for (int duo = 0; duo < 2; duo++) {
            const int row = rowBase + wr * 64 + mi * 16 + t4 + duo * 8;
            if (row >= M) continue;
            size_t orow = (size_t)row;
            if (embRemap) {
                int b = row / TLEN;
                orow = (size_t)b * LSEQ + 1 + (row - b * TLEN);
            }
            float scale = 1.f, addc = 0.f;
            if (lnIn) {
                float2 s0 = stats[row];
                float2 s1 = stats[NTOK + row];
                float sc_ = s0.x + s1.x, sq_ = s0.y + s1.y;
                float mm  = sc_ * (1.f / HID);
                float var = sq_ * (1.f / HID) - mm * mm;
                float rho = rsqrtf(4.f * var + LNEPS);
                scale = 2.f * rho;
                addc  = -2.f * rho * mm;
            }
            float ps = 0.f, pq = 0.f;
            #pragma unroll
            for (int nt = 0; nt < 4; nt++) {
                const int col = colBase + wc * 32 + nt * 8 + t2;
                const int bcol = qkvMode ? (col & 255) : col;
                float c0, c1;
                if (lnIn) {
                    c0 = scale * acc[mi][nt][duo*2 + 0] + addc * Svec[col]     + Cvec[col]     + bptr[bcol];
                    c1 = scale * acc[mi][nt][duo*2 + 1] + addc * Svec[col + 1] + Cvec[col + 1] + bptr[bcol + 1];
                } else {
                    c0 = acc[mi][nt][duo*2 + 0] + bptr[bcol];
                    c1 = acc[mi][nt][duo*2 + 1] + bptr[bcol + 1];
                }
                if (ep == 1)      { c0 = fmaxf(c0, 0.f) + KEPS; c1 = fmaxf(c1, 0.f) + KEPS; }
                else if (ep == 2) { c0 = fmaxf(c0, 0.f);        c1 = fmaxf(c1, 0.f); }
                if (statsOut) { ps += c0 + c1; pq += c0*c0 + c1*c1; }
                bf16 h0 = __float2bfloat16(c0), h1 = __float2bfloat16(c1);
                bf16 l0 = __float2bfloat16(c0 - __bfloat162float(h0));
                bf16 l1 = __float2bfloat16(c1 - __bfloat162float(h1));
                uint32_t hp = (uint32_t)*(uint16_t*)&h0 | ((uint32_t)*(uint16_t*)&h1 << 16);
                uint32_t lp = (uint32_t)*(uint16_t*)&l0 | ((uint32_t)*(uint16_t*)&l1 << 16);
                *(uint32_t*)(Ch + orow * N + col) = hp;
                *(uint32_t*)(Cl + orow * N + col) = lp;
            }
            if (statsOut) {
                ps += __shfl_xor_sync(0xffffffffu, ps, 1);
                ps += __shfl_xor_sync(0xffffffffu, ps, 2);
                pq += __shfl_xor_sync(0xffffffffu, pq, 1);
                pq += __shfl_xor_sync(0xffffffffu, pq, 2);
                if ((lane & 3) == 0) {
                    const int r128 = wr * 64 + mi * 16 + t4 + duo * 8;
                    sst[r128 * 8 + wc * 2 + 0] = ps;
                    sst[r128 * 8 + wc * 2 + 1] = pq;
                }
            }
        }
    }
    if (statsOut) {
        __syncthreads();
        if (tid < 128) {
            float s = sst[tid*8] + sst[tid*8+2] + sst[tid*8+4] + sst[tid*8+6];
            float q = sst[tid*8+1] + sst[tid*8+3] + sst[tid*8+5] + sst[tid*8+7];
            stats[(size_t)blockIdx.x * NTOK + rowBase + tid] = make_float2(s, q);
        }
    }
}

// ---------------- kv partials: register-tiled (4x4 per thread) ----------------
__global__ void ta_kv_reduce(const bf16* __restrict__ QKVh, const bf16* __restrict__ QKVl,
                             float* __restrict__ KVp, float* __restrict__ KSp) {
    const int s = blockIdx.x, h = blockIdx.y, b = blockIdx.z;
    const int tid = threadIdx.x;

    __shared__ float kp[32][36];
    __shared__ float vv[32][36];

    const size_t rowBase = (size_t)b * LSEQ + (size_t)s * (LSEQ / KSPLIT);

    const int row_ = tid >> 3;
    const int part = tid & 7;
    const int isV  = part >> 2;
    const int cseg = (part & 3) * 8;
    float* stDst = (isV ? &vv[row_][cseg] : &kp[row_][cseg]);

    const int tsub = tid >> 6;
    const int t64  = tid & 63;
    const int tm4  = (t64 >> 3) << 2;
    const int td4  = (t64 & 7) << 2;
    const bool ksaOwner = ((t64 & 7) == 0);

    float acc[4][4] = {};
    float ksa[4] = {0.f, 0.f, 0.f, 0.f};

    for (int c0 = 0; c0 < LSEQ / KSPLIT; c0 += 32) {
        {
            const size_t g = (rowBase + c0 + row_) * QKVW
                           + (isV ? 2*HID : HID) + h * DHEAD + cseg;
            uint4 h4 = *(const uint4*)(QKVh + g);
            uint4 l4 = *(const uint4*)(QKVl + g);
            float f[8];
            unp8(h4, l4, f);
            *(float4*)(stDst)     = make_float4(f[0], f[1], f[2], f[3]);
            *(float4*)(stDst + 4) = make_float4(f[4], f[5], f[6], f[7]);
        }
        __syncthreads();
        #pragma unroll
        for (int q = 0; q < 8; q++) {
            const int l = tsub * 8 + q;
            float4 kq = *(const float4*)&kp[l][tm4];
            float4 vq = *(const float4*)&vv[l][td4];
            float km[4] = {kq.x, kq.y, kq.z, kq.w};
            float vd[4] = {vq.x, vq.y, vq.z, vq.w};
            #pragma unroll
            for (int i = 0; i < 4; i++)
                #pragma unroll
                for (int j = 0; j < 4; j++)
                    acc[i][j] += km[i] * vd[j];
            if (ksaOwner) {
                #pragma unroll
                for (int i = 0; i < 4; i++) ksa[i] += km[i];
            }
        }
        __syncthreads();
    }

    const int bh = b * NHEAD + h;
    const size_t slot = (size_t)(s * 4 + tsub) * BATCH * NHEAD + bh;
    #pragma unroll
    for (int i = 0; i < 4; i++)
        *(float4*)&KVp[slot * 1024 + (tm4 + i) * 32 + td4] =
            make_float4(acc[i][0], acc[i][1], acc[i][2], acc[i][3]);
    if (ksaOwner)
        *(float4*)&KSp[slot * 32 + tm4] = make_float4(ksa[0], ksa[1], ksa[2], ksa[3]);
}

// ---------------- WeffT = blockdiag(kv) @ Wo ----------------
__global__ void ta_weff(const float* __restrict__ KVp, const float* __restrict__ Wo,
                        bf16* __restrict__ WH, bf16* __restrict__ WL,
                        float* __restrict__ W2f) {
    const int h = blockIdx.x, b = blockIdx.y;
    const int tid = threadIdx.x;
    const int bh = b * NHEAD + h;
    __shared__ float kvs[DHEAD*DHEAD];
    for (int i = tid; i < DHEAD*DHEAD; i += 256) {
        float v = 0.f;
        #pragma unroll
        for (int s = 0; s < KTOT; s++)
            v += KVp[((size_t)s * BATCH*NHEAD + bh) * 1024 + i];
        kvs[i] = v;
    }
    __syncthreads();

    float wcol[DHEAD];
    #pragma unroll
    for (int d = 0; d < DHEAD; d++)
        wcol[d] = Wo[((size_t)h*DHEAD + d)*HID + tid];

    for (int m = 0; m < DHEAD; m++) {
        const float4* k4 = (const float4*)&kvs[m*DHEAD];
        float a0 = 0.f;
        #pragma unroll
        for (int q = 0; q < 8; q++) {
            float4 kk = k4[q];
            a0 += kk.x*wcol[4*q] + kk.y*wcol[4*q+1] + kk.z*wcol[4*q+2] + kk.w*wcol[4*q+3];
        }
        size_t idx = ((size_t)b*HID + tid)*HID + h*DHEAD + m;
        bf16 hh = __float2bfloat16(a0);
        WH[idx] = hh;
        WL[idx] = __float2bfloat16(a0 - __bfloat162float(hh));
        W2f[((size_t)b*HID + h*DHEAD + m)*HID + tid] = a0;
    }
}

// ---------------- qp' = qp / (qp . ksum) ----------------
__global__ void ta_qpscale(const bf16* __restrict__ QKVh, const bf16* __restrict__ QKVl,
                           const float* __restrict__ KSp,
                           bf16* __restrict__ AH, bf16* __restrict__ AL) {
    __shared__ float kss[HID];
    const int b = blockIdx.y;
    const int tokBase = blockIdx.x * 32;
    const int tid = threadIdx.x;
    {
        const int h2 = tid >> 5, m = tid & 31;
        float v = 0.f;
        #pragma unroll
        for (int s = 0; s < KTOT; s++)
            v += KSp[((size_t)s * BATCH*NHEAD + b*NHEAD + h2) * 32 + m];
        kss[tid] = v;
    }
    __syncthreads();

    const int tok = tokBase + (tid >> 3);
    const int h   = tid & 7;
    const size_t qrow = ((size_t)b * LSEQ + tok) * QKVW + h * DHEAD;
    const size_t arow = ((size_t)b * LSEQ + tok) * HID  + h * DHEAD;

    float qv[DHEAD];
    #pragma unroll
    for (int g = 0; g < 4; g++) {
        uint4 h4 = *(const uint4*)(QKVh + qrow + g*8);
        uint4 l4 = *(const uint4*)(QKVl + qrow + g*8);
        unp8(h4, l4, qv + g*8);
    }
    float den = 0.f;
    #pragma unroll
    for (int m = 0; m < DHEAD; m++) den += qv[m] * kss[h*DHEAD + m];
    const float inv = 1.f / den;
    #pragma unroll
    for (int m = 0; m < DHEAD; m++) qv[m] *= inv;
    #pragma unroll
    for (int g = 0; g < 4; g++) {
        uint4 h4, l4;
        pk8(qv + g*8, h4, l4);
        *(uint4*)(AH + arow + g*8) = h4;
        *(uint4*)(AL + arow + g*8) = l4;
    }
}

// ---------------- last layer token-0: q + qp' (inline LN from z+stats) --------
__global__ void ta_lastq(const bf16* __restrict__ ZH, const bf16* __restrict__ ZL,
                         const float2* __restrict__ stats,
                         const float* __restrict__ sc2, const float* __restrict__ bi2,
                         const float* __restrict__ Wq3, const float* __restrict__ bq3,
                         const float* __restrict__ KSp, float* __restrict__ A0) {
    const int b = blockIdx.x, c = threadIdx.x;
    __shared__ float xs[HID], qps[HID], kss[HID];
    const size_t row = (size_t)b * LSEQ;
    {
        float2 s0 = stats[row];
        float2 s1 = stats[NTOK + row];
        float sc_ = s0.x + s1.x, sq_ = s0.y + s1.y;
        float mm  = sc_ * (1.f / HID);
        float var = sq_ * (1.f / HID) - mm * mm;
        float rho = rsqrtf(4.f * var + LNEPS);
        float cv  = hl(ZH, ZL, row * HID + c);
        xs[c] = 2.f * rho * (cv - mm) * sc2[c] + bi2[c];
    }
    {
        const int h2 = c >> 5, m = c & 31;
        float v = 0.f;
        #pragma unroll
        for (int s = 0; s < KTOT; s++)
            v += KSp[((size_t)s * BATCH*NHEAD + b*NHEAD + h2) * 32 + m];
        kss[c] = v;
    }
    __syncthreads();
    float q = bq3[c];
    #pragma unroll 8
    for (int d = 0; d < HID; d++) q += xs[d] * Wq3[(size_t)d*HID + c];
    float qp = fmaxf(q, 0.f) + KEPS;
    qps[c] = qp;
    __syncthreads();
    const int h = c >> 5;
    float den = 0.f;
    #pragma unroll
    for (int m = 0; m < DHEAD; m++) den += qps[h*DHEAD + m] * kss[h*DHEAD + m];
    A0[b*HID + c] = qp / den;
}

__global__ void ta_lastmile(const float* __restrict__ A0, const float* __restrict__ W2f,
                            const float* __restrict__ bo3,
                            const float* __restrict__ ln1s3, const float* __restrict__ ln1b3,
                            const float* __restrict__ W1_3, const float* __restrict__ b1_3,
                            const float* __restrict__ W2_3, const float* __restrict__ b2_3,
                            const float* __restrict__ ln2s3, const float* __restrict__ ln2b3,
                            const float* __restrict__ qpW, const float* __restrict__ qpb,
                            float* __restrict__ out) {
    const int b = blockIdx.x, c = threadIdx.x;
    const int wid = c >> 5, lane = c & 31;
    __shared__ float a0[HID], x1[HID], f[FFD], xo[HID], sred[16];

    a0[c] = A0[b*HID + c];
    __syncthreads();

    float o = bo3[c];
    const float* w = W2f + (size_t)b*HID*HID;
    #pragma unroll 8
    for (int d = 0; d < HID; d++) o += a0[d] * w[(size_t)d*HID + c];
    float v = 2.f * o;

    {
        float s = v, q = v * v;
        #pragma unroll
        for (int off = 16; off; off >>= 1) {
            s += __shfl_xor_sync(0xffffffffu, s, off);
            q += __shfl_xor_sync(0xffffffffu, q, off);
        }
        if (lane == 0) { sred[wid] = s; sred[8 + wid] = q; }
        __syncthreads();
        float ts = 0.f, tq = 0.f;
        #pragma unroll
        for (int i = 0; i < 8; i++) { ts += sred[i]; tq += sred[8 + i]; }
        const float mean = ts * (1.f / HID);
        const float var  = tq * (1.f / HID) - mean * mean;
        const float rr   = rsqrtf(var + LNEPS);
        x1[c] = (v - mean) * rr * ln1s3[c] + ln1b3[c];
        __syncthreads();
    }

    #pragma unroll
    for (int jj = 0; jj < 4; jj++) {
        const int j = c + jj * 256;
        float s = b1_3[j];
        #pragma unroll 8
        for (int d = 0; d < HID; d++) s += x1[d] * W1_3[(size_t)d*FFD + j];
        f[j] = fmaxf(s, 0.f);
    }
    __syncthreads();

    float z = b2_3[c];
    #pragma unroll 8
    for (int j = 0; j < FFD; j++) z += f[j] * W2_3[(size_t)j*HID + c];
    float v2 = 2.f * z;

    {
        float s = v2, q = v2 * v2;
        #pragma unroll
        for (int off = 16; off; off >>= 1) {
            s += __shfl_xor_sync(0xffffffffu, s, off);
            q += __shfl_xor_sync(0xffffffffu, q, off);
        }
        __syncthreads();
        if (lane == 0) { sred[wid] = s; sred[8 + wid] = q; }
        __syncthreads();
        float ts = 0.f, tq = 0.f;
        #pragma unroll
        for (int i = 0; i < 8; i++) { ts += sred[i]; tq += sred[8 + i]; }
        const float mean = ts * (1.f / HID);
        const float var  = tq * (1.f / HID) - mean * mean;
        const float rr   = rsqrtf(var + LNEPS);
        xo[c] = (v2 - mean) * rr * ln2s3[c] + ln2b3[c];
    }
    out[b*HID + c] = xo[c];
    __syncthreads();

    if (c < 32) {
        float s = qpb[c];
        #pragma unroll 8
        for (int d = 0; d < HID; d++) s += xo[d] * qpW[d*32 + c];
        out[BATCH*HID + b*32 + c] = s;
    }
}

// ---------------- launcher ----------------
extern "C" void kernel_launch(void* const* d_in, const int* in_sizes, int n_in,
                              void* d_out, int out_size) {
    const float* hidden = (const float*)d_in[0];
    const float* ins    = (const float*)d_in[1];
    const unsigned char* resets = (const unsigned char*)d_in[2];
    const float* embW = (const float*)d_in[3];
    const float* embb = (const float*)d_in[4];
    const float* Wq = (const float*)d_in[5];
    const float* bq = (const float*)d_in[6];
    const float* Wk = (const float*)d_in[7];
    const float* bk = (const float*)d_in[8];
    const float* Wv = (const float*)d_in[9];
    const float* bv = (const float*)d_in[10];
    const float* Wo = (const float*)d_in[11];
    const float* bo = (const float*)d_in[12];
    const float* ln1s = (const float*)d_in[13];
    const float* ln1b = (const float*)d_in[14];
    const float* W1 = (const float*)d_in[15];
    const float* b1 = (const float*)d_in[16];
    const float* W2 = (const float*)d_in[17];
    const float* b2 = (const float*)d_in[18];
    const float* ln2s = (const float*)d_in[19];
    const float* ln2b = (const float*)d_in[20];
    const float* qpW = (const float*)d_in[21];
    const float* qpb = (const float*)d_in[22];

    bf16 *xh,*xl,*qkvh,*qkvl,*ah,*al,*zh,*zl,*fh,*fl,*insh,*insl,*wth,*wtl,*weh,*wel;
    float *kvp, *ksp, *w2f, *a0, *sv, *cv;
    float2 *stats;
    cudaGetSymbolAddress((void**)&xh,   g_xh);   cudaGetSymbolAddress((void**)&xl,   g_xl);
    cudaGetSymbolAddress((void**)&qkvh, g_qkvh); cudaGetSymbolAddress((void**)&qkvl, g_qkvl);
    cudaGetSymbolAddress((void**)&ah,   g_ah);   cudaGetSymbolAddress((void**)&al,   g_al);
    cudaGetSymbolAddress((void**)&zh,   g_zh);   cudaGetSymbolAddress((void**)&zl,   g_zl);
    cudaGetSymbolAddress((void**)&fh,   g_fh);   cudaGetSymbolAddress((void**)&fl,   g_fl);
    cudaGetSymbolAddress((void**)&insh, g_insh); cudaGetSymbolAddress((void**)&insl, g_insl);
    cudaGetSymbolAddress((void**)&wth,  g_wth);  cudaGetSymbolAddress((void**)&wtl,  g_wtl);
    cudaGetSymbolAddress((void**)&weh,  g_weffh);cudaGetSymbolAddress((void**)&wel,  g_weffl);
    cudaGetSymbolAddress((void**)&kvp,  g_kvpart); cudaGetSymbolAddress((void**)&ksp, g_kspart);
    cudaGetSymbolAddress((void**)&w2f,  g_weff2);  cudaGetSymbolAddress((void**)&a0,  g_a0);
    cudaGetSymbolAddress((void**)&sv,   g_sv);   cudaGetSymbolAddress((void**)&cv,   g_cv);
    cudaGetSymbolAddress((void**)&stats,g_stats);

    const int GEMM_SMEM = 98304;
    cudaFuncSetAttribute(ta_gemm_bf16, cudaFuncAttributeMaxDynamicSharedMemorySize, GEMM_SMEM);

    ta_wconv_all<<<dim3(1024, 25), 256>>>(embW, Wq, Wk, Wv, Wo, W1, W2, ln1s, ln2s, wth, wtl);
    ta_snc<<<cdiv(SNC_TOTAL, 256), 256>>>(Wq, Wk, Wv, W1, ln1s, ln1b, ln2s, ln2b, sv, cv);
    {
        int n = BATCH*TLEN*OBSD + BATCH*HID;
        ta_prep<<<cdiv(n,256), 256>>>(ins, hidden, resets, insh, insl, xh, xl);
    }
    {
        int M = BATCH * TLEN;
        ta_gemm_bf16<<<dim3(HID/128, cdiv(M,128)), 256, GEMM_SMEM>>>(
            insh, insl, wth, wtl, embb, embb, embb, sv, cv, stats,
            xh, xl, M, OBSD, HID, 0, 1);
    }

    const dim3 gqkv(QKVW/128, NTOK/128);  // (6, 512)
    const dim3 gkv (4,        NTOK/128);  // kv-only, col tiles 2..5
    const dim3 g256(HID/128,  NTOK/128);  // (2, 512)
    const dim3 gff (FFD/128,  NTOK/128);  // (8, 512)

    for (int l = 0; l < NLAY; l++) {
        const bool last = (l == NLAY - 1);
        size_t base = WT_EMB_SZ + (size_t)l * WT_LAYER_SZ;
        const bf16 *qkvwh = wth + base,          *qkvwl = wtl + base;
        const bf16 *w1h   = wth + base + 262144, *w1l   = wtl + base + 262144;
        const bf16 *w2h   = wth + base + 524288, *w2l   = wtl + base + 524288;
        const float *svq = sv + 3*FFD + (l-1)*QKVW;   // valid for l>=1
        const float *cvq = cv + 3*FFD + (l-1)*QKVW;

        if (!last) {
            if (l == 0) {
                ta_gemm_bf16<<<gqkv, 256, GEMM_SMEM>>>(xh, xl, qkvwh, qkvwl,
                                                       bq + l*HID, bk + l*HID, bv + l*HID,
                                                       sv, cv, stats,
                                                       qkvh, qkvl, NTOK, HID, QKVW, 0, 2);
            } else {
                ta_gemm_bf16<<<gqkv, 256, GEMM_SMEM>>>(zh, zl, qkvwh, qkvwl,
                                                       bq + l*HID, bk + l*HID, bv + l*HID,
                                                       svq, cvq, stats,
                                                       qkvh, qkvl, NTOK, HID, QKVW, 0, 2 | 64);
            }
        } else {
            ta_gemm_bf16<<<gkv, 256, GEMM_SMEM>>>(zh, zl, qkvwh, qkvwl,
                                                  bq + l*HID, bk + l*HID, bv + l*HID,
                                                  svq, cvq, stats,
                                                  qkvh, qkvl, NTOK, HID, QKVW, 0, 2 | 8 | 64);
        }
        ta_kv_reduce<<<dim3(KSPLIT, NHEAD, BATCH), 256>>>(qkvh, qkvl, kvp, ksp);
        ta_weff<<<dim3(NHEAD, BATCH), 256>>>(kvp, Wo + (size_t)l*HID*HID, weh, wel, w2f);

        if (!last) {
            ta_qpscale<<<dim3(LSEQ/32, BATCH), 256>>>(qkvh, qkvl, ksp, ah, al);
            // o-proj -> z, with per-row stats for ln1
            ta_gemm_bf16<<<g256, 256, GEMM_SMEM>>>(ah, al, weh, wel,
                                                   bo + l*HID, bo + l*HID, bo + l*HID,
                                                   sv, cv, stats,
                                                   zh, zl, NTOK, HID, HID, 0, 4 | 32);
            // ffn1 consumes z + ln1 fold -> f (relu)
            ta_gemm_bf16<<<gff, 256, GEMM_SMEM>>>(zh, zl, w1h, w1l,
                                                  b1 + l*FFD, b1 + l*FFD, b1 + l*FFD,
                                                  sv + l*FFD, cv + l*FFD, stats,
                                                  fh, fl, NTOK, HID, FFD, 2, 64);
            // ffn2 -> z, with per-row stats for ln2
            ta_gemm_bf16<<<g256, 256, GEMM_SMEM>>>(fh, fl, w2h, w2l,
                                                   b2 + l*HID, b2 + l*HID, b2 + l*HID,
                                                   sv, cv, stats,
                                                   zh, zl, NTOK, FFD, HID, 0, 32);
        } else {
            ta_lastq<<<BATCH, 256>>>(zh, zl, stats, ln2s + 2*HID, ln2b + 2*HID,
                                     Wq + (size_t)l*HID*HID, bq + l*HID, ksp, a0);
            ta_lastmile<<<BATCH, 256>>>(a0, w2f, bo + l*HID,
                                        ln1s + l*HID, ln1b + l*HID,
                                        W1 + (size_t)l*HID*FFD, b1 + l*FFD,
                                        W2 + (size_t)l*FFD*HID, b2 + l*HID,
                                        ln2s + l*HID, ln2b + l*HID,
                                        qpW, qpb, (float*)d_out);
        }
    }
}

// round 17
// speedup vs baseline: 2.3323x; 1.8577x over previous
#include <cuda_runtime.h>
#include <cuda_fp16.h>
#include <cstdint>

// ---------------- problem constants ----------------
#define BATCH 16
#define TLEN  4095
#define LSEQ  4096          // TLEN + 1
#define NTOK  (BATCH*LSEQ)  // 65536
#define OBSD  128
#define HID   256
#define NHEAD 8
#define DHEAD 32
#define FFD   1024
#define NLAY  4
#define QKVW  (3*HID)       // 768
#define KSPLIT 8
#define KTOT   32
#define KEPS  1e-3f
#define LNEPS 1e-6f

typedef __half fp16;

// ---------------- device scratch (fp16 activations, single precision pass) ----
__device__ fp16 g_x  [(size_t)NTOK*HID];
__device__ fp16 g_qkv[(size_t)NTOK*QKVW];
__device__ fp16 g_a  [(size_t)NTOK*HID];
__device__ fp16 g_z  [(size_t)NTOK*HID];
__device__ fp16 g_f  [(size_t)NTOK*FFD];
__device__ fp16 g_ins[(size_t)(BATCH*TLEN)*OBSD];
__device__ float g_kvpart[(size_t)KTOT*BATCH*NHEAD*DHEAD*DHEAD];
__device__ float g_kspart[(size_t)KTOT*BATCH*NHEAD*DHEAD];
__device__ fp16 g_weffh[BATCH*HID*HID];            // fp16 WT[c][d] per batch
__device__ float g_weff2[(size_t)BATCH*HID*HID];   // fp32 [b][d][c] for last-mile
__device__ float g_a0[BATCH*HID];
__device__ float2 g_stats[2*NTOK];
#define SNC_TOTAL (3*FFD + 3*QKVW)
__device__ float g_sv[SNC_TOTAL];
__device__ float g_cv[SNC_TOTAL];

#define WT_EMB_SZ   (HID*OBSD)
#define WT_LAYER_SZ (4*HID*HID + 2*HID*FFD)
#define WT_TOTAL    (WT_EMB_SZ + NLAY*WT_LAYER_SZ)
__device__ fp16 g_wt[WT_TOTAL];

static inline int cdiv(int a, int b) { return (a + b - 1) / b; }

// ---------------- helpers ----------------
__device__ __forceinline__ uint32_t smem_u32(const void* p) {
    uint32_t a;
    asm("{ .reg .u64 t; cvta.to.shared.u64 t, %1; cvt.u32.u64 %0, t; }" : "=r"(a) : "l"(p));
    return a;
}
__device__ __forceinline__ void unp8h(const uint4& v, float* f) {
    const __half2* p = (const __half2*)&v;
    #pragma unroll
    for (int i = 0; i < 4; i++) {
        float2 t = __half22float2(p[i]);
        f[2*i] = t.x; f[2*i+1] = t.y;
    }
}
__device__ __forceinline__ uint4 pk8h(const float* f) {
    uint4 v;
    __half2* p = (__half2*)&v;
    #pragma unroll
    for (int i = 0; i < 4; i++)
        p[i] = __floats2half2_rn(f[2*i], f[2*i+1]);
    return v;
}

#define LDSM4(r, addr)                                                     \
    asm volatile("ldmatrix.sync.aligned.m8n8.x4.shared.b16 "               \
                 "{%0,%1,%2,%3}, [%4];"                                    \
                 : "=r"((r)[0]), "=r"((r)[1]), "=r"((r)[2]), "=r"((r)[3])  \
                 : "r"(addr))

#define MMA_F16(d, a, b0, b1)                                              \
    asm volatile("mma.sync.aligned.m16n8k16.row.col.f32.f16.f16.f32 "      \
                 "{%0,%1,%2,%3},{%4,%5,%6,%7},{%8,%9},{%0,%1,%2,%3};"      \
                 : "+f"((d)[0]), "+f"((d)[1]), "+f"((d)[2]), "+f"((d)[3])  \
                 : "r"((a)[0]), "r"((a)[1]), "r"((a)[2]), "r"((a)[3]),     \
                   "r"(b0), "r"(b1))

__device__ __forceinline__ void cpa16(uint32_t dst, const void* src, int sz) {
    asm volatile("cp.async.cg.shared.global [%0], [%1], 16, %2;"
                 :: "r"(dst), "l"(__cvta_generic_to_global(src)), "r"(sz));
}

// ---------------- weight conversion (transpose + fp16; LN-scale fold) --------
__global__ void ta_wconv_all(const float* __restrict__ embW,
                             const float* __restrict__ Wq, const float* __restrict__ Wk,
                             const float* __restrict__ Wv, const float* __restrict__ Wo,
                             const float* __restrict__ W1, const float* __restrict__ W2,
                             const float* __restrict__ ln1s, const float* __restrict__ ln2s,
                             fp16* __restrict__ wt) {
    const int seg = blockIdx.y;
    const float* src;
    const float* scv = nullptr;
    int K, N;
    size_t dst;
    if (seg == 0) {
        src = embW; K = OBSD; N = HID; dst = 0;
    } else {
        const int l = (seg - 1) / 6, m = (seg - 1) % 6;
        const size_t base = WT_EMB_SZ + (size_t)l * WT_LAYER_SZ;
        switch (m) {
            case 0: src = Wq + (size_t)l*HID*HID; K = HID; N = HID; dst = base;
                    if (l >= 1) scv = ln2s + (l-1)*HID; break;
            case 1: src = Wk + (size_t)l*HID*HID; K = HID; N = HID; dst = base + 65536;
                    if (l >= 1) scv = ln2s + (l-1)*HID; break;
            case 2: src = Wv + (size_t)l*HID*HID; K = HID; N = HID; dst = base + 131072;
                    if (l >= 1) scv = ln2s + (l-1)*HID; break;
            case 3: src = Wo + (size_t)l*HID*HID; K = HID; N = HID; dst = base + 196608; break;
            case 4: src = W1 + (size_t)l*HID*FFD; K = HID; N = FFD; dst = base + 262144;
                    if (l < 3) scv = ln1s + l*HID; break;
            default:src = W2 + (size_t)l*FFD*HID; K = FFD; N = HID; dst = base + 524288; break;
        }
    }
    int i = blockIdx.x * 256 + threadIdx.x;
    if (i >= N * K) return;
    int n = i / K, k = i - n * K;
    float w = src[(size_t)k * N + n];
    if (scv) w *= scv[k];
    wt[dst + i] = __float2half_rn(w);
}

// ---------------- S = sc^T W, C = bi^T W vectors ----------------
__global__ void ta_snc(const float* __restrict__ Wq, const float* __restrict__ Wk,
                       const float* __restrict__ Wv, const float* __restrict__ W1,
                       const float* __restrict__ ln1s, const float* __restrict__ ln1b,
                       const float* __restrict__ ln2s, const float* __restrict__ ln2b,
                       float* __restrict__ SV, float* __restrict__ CV) {
    int idx = blockIdx.x * 256 + threadIdx.x;
    if (idx >= SNC_TOTAL) return;
    float S = 0.f, C = 0.f;
    if (idx < 3*FFD) {
        const int l = idx / FFD, n = idx % FFD;
        const float* W = W1 + (size_t)l*HID*FFD;
        const float* s = ln1s + l*HID;
        const float* b = ln1b + l*HID;
        for (int k = 0; k < HID; k++) {
            float w = W[(size_t)k*FFD + n];
            S += s[k]*w; C += b[k]*w;
        }
    } else {
        const int j = idx - 3*FFD;
        const int l = j / QKVW + 1, n = j % QKVW;
        const int sg = n >> 8, nn = n & 255;
        const float* W = (sg == 0 ? Wq : sg == 1 ? Wk : Wv) + (size_t)l*HID*HID;
        const float* s = ln2s + (l-1)*HID;
        const float* b = ln2b + (l-1)*HID;
        for (int k = 0; k < HID; k++) {
            float w = W[(size_t)k*HID + nn];
            S += s[k]*w; C += b[k]*w;
        }
    }
    SV[idx] = S; CV[idx] = C;
}

// ---------------- split ins + init hidden row ----------------
__global__ void ta_prep(const float* __restrict__ ins,
                        const float* __restrict__ hs,
                        const unsigned char* __restrict__ resets,
                        fp16* __restrict__ IF, fp16* __restrict__ X) {
    const int nIns = BATCH * TLEN * OBSD;
    int i = blockIdx.x * 256 + threadIdx.x;
    if (i < nIns) {
        IF[i] = __float2half_rn(ins[i]);
    } else {
        int j = i - nIns;
        if (j < BATCH * HID) {
            int b = j >> 8, c = j & 255;
            float v = resets[b] ? 0.f : hs[b*HID + c];
            X[(size_t)b*LSEQ*HID + c] = __float2half_rn(v);
        }
    }
}

// ---------------- single-pass fp16 MMA GEMM (3-stage, swizzled) --------------
// Block 128x128, 8 warps (2x4), warp tile 64x32. stage = A 8K + B 8K = 16KB.
// flags: bit0 embRemap, bit1 qkvMode, bit2 batchedB, bit3 colOff+2 (kv-only),
//        bit5 statsOut, bit6 lnIn
__global__ __launch_bounds__(256, 2)
void ta_gemm_f16(const fp16* __restrict__ A, const fp16* __restrict__ B,
                 const float* __restrict__ bias0, const float* __restrict__ bias1,
                 const float* __restrict__ bias2,
                 const float* __restrict__ Svec, const float* __restrict__ Cvec,
                 float2* __restrict__ stats,
                 fp16* __restrict__ C,
                 int M, int K, int N, int epi, int flags) {
    extern __shared__ char smem[];
    const uint32_t smu = smem_u32(smem);

    const int tid  = threadIdx.x;
    const int wid  = tid >> 5;
    const int lane = tid & 31;
    const int wr   = wid >> 2;
    const int wc   = wid & 3;
    const int rowBase = blockIdx.y * 128;
    const int colBase = (blockIdx.x + ((flags & 8) ? 2 : 0)) * 128;

    if (flags & 4) {
        const size_t boff = (size_t)(rowBase >> 12) * HID * HID;
        B += boff;
    }

    const int r  = tid >> 2;
    const int ch = tid & 3;
    const uint32_t stOff  = (uint32_t)(r * 64 + ((ch ^ ((r >> 1) & 3)) << 4));
    const uint32_t stOff2 = (uint32_t)((r + 64) * 64 + ((ch ^ (((r + 64) >> 1) & 3)) << 4));

    const int r15 = lane & 15;
    const int hi_ = lane >> 4;
    const int sw  = (r15 >> 1) & 3;
    const uint32_t rowB  = (uint32_t)(r15 * 64);
    const uint32_t co0   = rowB + (uint32_t)(((hi_    ) ^ sw) << 4);
    const uint32_t co1   = rowB + (uint32_t)(((2 + hi_) ^ sw) << 4);
    const uint32_t aWarp = (uint32_t)(wr * 4096);
    const uint32_t bWarp = (uint32_t)(wc * 2048);

    float acc[4][4][4] = {};

    auto load_stage = [&](int st, int kt) {
        const uint32_t sb = smu + (uint32_t)st * 16384u;
        const int kOff = kt * 32 + ch * 8;
        {
            const int grow = rowBase + r;
            const int sz = (grow < M) ? 16 : 0;
            const size_t asrc = (size_t)(sz ? grow : 0) * K + kOff;
            cpa16(sb + stOff, A + asrc, sz);
            const size_t bsrc = (size_t)(colBase + r) * K + kOff;
            cpa16(sb + 8192u + stOff, B + bsrc, 16);
        }
        {
            const int grow = rowBase + r + 64;
            const int sz = (grow < M) ? 16 : 0;
            const size_t asrc = (size_t)(sz ? grow : 0) * K + kOff;
            cpa16(sb + stOff2, A + asrc, sz);
            const size_t bsrc = (size_t)(colBase + r + 64) * K + kOff;
            cpa16(sb + 8192u + stOff2, B + bsrc, 16);
        }
        asm volatile("cp.async.commit_group;");
    };

    auto compute = [&](int st) {
        const uint32_t sb = smu + (uint32_t)st * 16384u;
        const uint32_t aB = sb + aWarp;
        const uint32_t bB = sb + 8192u + bWarp;
        #pragma unroll
        for (int ks = 0; ks < 2; ks++) {
            const uint32_t co = ks ? co1 : co0;
            uint32_t b[2][4];
            LDSM4(b[0], bB + co);
            LDSM4(b[1], bB + 1024u + co);
            uint32_t a[4][4];
            #pragma unroll
            for (int mi = 0; mi < 4; mi++) LDSM4(a[mi], aB + mi * 1024u + co);
            #pragma unroll
            for (int mi = 0; mi < 4; mi++)
                #pragma unroll
                for (int nt = 0; nt < 4; nt++)
                    MMA_F16(acc[mi][nt], a[mi], b[nt >> 1][nt & 1], b[nt >> 1][(nt & 1) + 2]);
        }
    };

    const int nk = K >> 5;
    load_stage(0, 0);
    load_stage(1, 1);
    int cs = 0, ls = 2;
    for (int kt = 0; kt < nk; kt++) {
        if (kt == nk - 1) asm volatile("cp.async.wait_group 0;");
        else              asm volatile("cp.async.wait_group 1;");
        __syncthreads();
        if (kt + 2 < nk) {
            load_stage(ls, kt + 2);
            ls = (ls == 2) ? 0 : ls + 1;
        }
        compute(cs);
        cs = (cs == 2) ? 0 : cs + 1;
    }

    // ---- epilogue
    const bool embRemap = flags & 1;
    const bool qkvMode  = flags & 2;
    const bool statsOut = flags & 32;
    const bool lnIn     = flags & 64;
    float* sst = (float*)smem;
    if (statsOut) __syncthreads();

    const float* bptr = bias0;
    int ep = epi;
    if (qkvMode) {
        int seg = colBase >> 8;
        bptr = (seg == 0) ? bias0 : (seg == 1) ? bias1 : bias2;
        ep = (seg < 2) ? 1 : 0;
    }
    const int t4 = lane >> 2;
    const int t2 = (lane & 3) << 1;
    #pragma unroll
    for (int mi = 0; mi < 4; mi++) {
        #pragma unroll
        for (int duo = 0; duo < 2; duo++) {
            const int row = rowBase + wr * 64 + mi * 16 + t4 + duo * 8;
            if (row >= M) continue;
            size_t orow = (size_t)row;
            if (embRemap) {
                int b = row / TLEN;
                orow = (size_t)b * LSEQ + 1 + (row - b * TLEN);
            }
            float scale = 1.f, addc = 0.f;
            if (lnIn) {
                float2 s0 = stats[row];
                float2 s1 = stats[NTOK + row];
                float sc_ = s0.x + s1.x, sq_ = s0.y + s1.y;
                float mm  = sc_ * (1.f / HID);
                float var = sq_ * (1.f / HID) - mm * mm;
                float rho = rsqrtf(4.f * var + LNEPS);
                scale = 2.f * rho;
                addc  = -2.f * rho * mm;
            }
            float ps = 0.f, pq = 0.f;
            #pragma unroll
            for (int nt = 0; nt < 4; nt++) {
                const int col = colBase + wc * 32 + nt * 8 + t2;
                const int bcol = qkvMode ? (col & 255) : col;
                float c0, c1;
                if (lnIn) {
                    c0 = scale * acc[mi][nt][duo*2 + 0] + addc * Svec[col]     + Cvec[col]     + bptr[bcol];
                    c1 = scale * acc[mi][nt][duo*2 + 1] + addc * Svec[col + 1] + Cvec[col + 1] + bptr[bcol + 1];
                } else {
                    c0 = acc[mi][nt][duo*2 + 0] + bptr[bcol];
                    c1 = acc[mi][nt][duo*2 + 1] + bptr[bcol + 1];
                }
                if (ep == 1)      { c0 = fmaxf(c0, 0.f) + KEPS; c1 = fmaxf(c1, 0.f) + KEPS; }
                else if (ep == 2) { c0 = fmaxf(c0, 0.f);        c1 = fmaxf(c1, 0.f); }
                if (statsOut) { ps += c0 + c1; pq += c0*c0 + c1*c1; }
                __half2 hv = __floats2half2_rn(c0, c1);
                *(uint32_t*)(C + orow * N + col) = *(uint32_t*)&hv;
            }
            if (statsOut) {
                ps += __shfl_xor_sync(0xffffffffu, ps, 1);
                ps += __shfl_xor_sync(0xffffffffu, ps, 2);
                pq += __shfl_xor_sync(0xffffffffu, pq, 1);
                pq += __shfl_xor_sync(0xffffffffu, pq, 2);
                if ((lane & 3) == 0) {
                    const int r128 = wr * 64 + mi * 16 + t4 + duo * 8;
                    sst[r128 * 8 + wc * 2 + 0] = ps;
                    sst[r128 * 8 + wc * 2 + 1] = pq;
                }
            }
        }
    }
    if (statsOut) {
        __syncthreads();
        if (tid < 128) {
            float s = sst[tid*8] + sst[tid*8+2] + sst[tid*8+4] + sst[tid*8+6];
            float q = sst[tid*8+1] + sst[tid*8+3] + sst[tid*8+5] + sst[tid*8+7];
            stats[(size_t)blockIdx.x * NTOK + rowBase + tid] = make_float2(s, q);
        }
    }
}

// ---------------- kv partials: register-tiled (4x4 per thread) ----------------
__global__ void ta_kv_reduce(const fp16* __restrict__ QKV,
                             float* __restrict__ KVp, float* __restrict__ KSp) {
    const int s = blockIdx.x, h = blockIdx.y, b = blockIdx.z;
    const int tid = threadIdx.x;

    __shared__ float kp[32][36];
    __shared__ float vv[32][36];

    const size_t rowBase = (size_t)b * LSEQ + (size_t)s * (LSEQ / KSPLIT);

    const int row_ = tid >> 3;
    const int part = tid & 7;
    const int isV  = part >> 2;
    const int cseg = (part & 3) * 8;
    float* stDst = (isV ? &vv[row_][cseg] : &kp[row_][cseg]);

    const int tsub = tid >> 6;
    const int t64  = tid & 63;
    const int tm4  = (t64 >> 3) << 2;
    const int td4  = (t64 & 7) << 2;
    const bool ksaOwner = ((t64 & 7) == 0);

    float acc[4][4] = {};
    float ksa[4] = {0.f, 0.f, 0.f, 0.f};

    for (int c0 = 0; c0 < LSEQ / KSPLIT; c0 += 32) {
        {
            const size_t g = (rowBase + c0 + row_) * QKVW
                           + (isV ? 2*HID : HID) + h * DHEAD + cseg;
            uint4 v = *(const uint4*)(QKV + g);
            float f[8];
            unp8h(v, f);
            *(float4*)(stDst)     = make_float4(f[0], f[1], f[2], f[3]);
            *(float4*)(stDst + 4) = make_float4(f[4], f[5], f[6], f[7]);
        }
        __syncthreads();
        #pragma unroll
        for (int q = 0; q < 8; q++) {
            const int l = tsub * 8 + q;
            float4 kq = *(const float4*)&kp[l][tm4];
            float4 vq = *(const float4*)&vv[l][td4];
            float km[4] = {kq.x, kq.y, kq.z, kq.w};
            float vd[4] = {vq.x, vq.y, vq.z, vq.w};
            #pragma unroll
            for (int i = 0; i < 4; i++)
                #pragma unroll
                for (int j = 0; j < 4; j++)
                    acc[i][j] += km[i] * vd[j];
            if (ksaOwner) {
                #pragma unroll
                for (int i = 0; i < 4; i++) ksa[i] += km[i];
            }
        }
        __syncthreads();
    }

    const int bh = b * NHEAD + h;
    const size_t slot = (size_t)(s * 4 + tsub) * BATCH * NHEAD + bh;
    #pragma unroll
    for (int i = 0; i < 4; i++)
        *(float4*)&KVp[slot * 1024 + (tm4 + i) * 32 + td4] =
            make_float4(acc[i][0], acc[i][1], acc[i][2], acc[i][3]);
    if (ksaOwner)
        *(float4*)&KSp[slot * 32 + tm4] = make_float4(ksa[0], ksa[1], ksa[2], ksa[3]);
}

// ---------------- WeffT = blockdiag(kv) @ Wo ----------------
__global__ void ta_weff(const float* __restrict__ KVp, const float* __restrict__ Wo,
                        fp16* __restrict__ WE, float* __restrict__ W2f) {
    const int h = blockIdx.x, b = blockIdx.y;
    const int tid = threadIdx.x;
    const int bh = b * NHEAD + h;
    __shared__ float kvs[DHEAD*DHEAD];
    for (int i = tid; i < DHEAD*DHEAD; i += 256) {
        float v = 0.f;
        #pragma unroll
        for (int s = 0; s < KTOT; s++)
            v += KVp[((size_t)s * BATCH*NHEAD + bh) * 1024 + i];
        kvs[i] = v;
    }
    __syncthreads();

    float wcol[DHEAD];
    #pragma unroll
    for (int d = 0; d < DHEAD; d++)
        wcol[d] = Wo[((size_t)h*DHEAD + d)*HID + tid];

    for (int m = 0; m < DHEAD; m++) {
        const float4* k4 = (const float4*)&kvs[m*DHEAD];
        float a0 = 0.f;
        #pragma unroll
        for (int q = 0; q < 8; q++) {
            float4 kk = k4[q];
            a0 += kk.x*wcol[4*q] + kk.y*wcol[4*q+1] + kk.z*wcol[4*q+2] + kk.w*wcol[4*q+3];
        }
        WE[((size_t)b*HID + tid)*HID + h*DHEAD + m] = __float2half_rn(a0);
        W2f[((size_t)b*HID + h*DHEAD + m)*HID + tid] = a0;
    }
}

// ---------------- qp' = qp / (qp . ksum) ----------------
__global__ void ta_qpscale(const fp16* __restrict__ QKV, const float* __restrict__ KSp,
                           fp16* __restrict__ Aout) {
    __shared__ float kss[HID];
    const int b = blockIdx.y;
    const int tokBase = blockIdx.x * 32;
    const int tid = threadIdx.x;
    {
        const int h2 = tid >> 5, m = tid & 31;
        float v = 0.f;
        #pragma unroll
        for (int s = 0; s < KTOT; s++)
            v += KSp[((size_t)s * BATCH*NHEAD + b*NHEAD + h2) * 32 + m];
        kss[tid] = v;
    }
    __syncthreads();

    const int tok = tokBase + (tid >> 3);
    const int h   = tid & 7;
    const size_t qrow = ((size_t)b * LSEQ + tok) * QKVW + h * DHEAD;
    const size_t arow = ((size_t)b * LSEQ + tok) * HID  + h * DHEAD;

    float qv[DHEAD];
    #pragma unroll
    for (int g = 0; g < 4; g++) {
        uint4 v = *(const uint4*)(QKV + qrow + g*8);
        unp8h(v, qv + g*8);
    }
    float den = 0.f;
    #pragma unroll
    for (int m = 0; m < DHEAD; m++) den += qv[m] * kss[h*DHEAD + m];
    const float inv = 1.f / den;
    #pragma unroll
    for (int m = 0; m < DHEAD; m++) qv[m] *= inv;
    #pragma unroll
    for (int g = 0; g < 4; g++)
        *(uint4*)(Aout + arow + g*8) = pk8h(qv + g*8);
}

// ---------------- last layer token-0: q + qp' (inline LN from z+stats) --------
__global__ void ta_lastq(const fp16* __restrict__ Z,
                         const float2* __restrict__ stats,
                         const float* __restrict__ sc2, const float* __restrict__ bi2,
                         const float* __restrict__ Wq3, const float* __restrict__ bq3,
                         const float* __restrict__ KSp, float* __restrict__ A0) {
    const int b = blockIdx.x, c = threadIdx.x;
    __shared__ float xs[HID], qps[HID], kss[HID];
    const size_t row = (size_t)b * LSEQ;
    {
        float2 s0 = stats[row];
        float2 s1 = stats[NTOK + row];
        float sc_ = s0.x + s1.x, sq_ = s0.y + s1.y;
        float mm  = sc_ * (1.f / HID);
        float var = sq_ * (1.f / HID) - mm * mm;
        float rho = rsqrtf(4.f * var + LNEPS);
        float cv  = __half2float(Z[row * HID + c]);
        xs[c] = 2.f * rho * (cv - mm) * sc2[c] + bi2[c];
    }
    {
        const int h2 = c >> 5, m = c & 31;
        float v = 0.f;
        #pragma unroll
        for (int s = 0; s < KTOT; s++)
            v += KSp[((size_t)s * BATCH*NHEAD + b*NHEAD + h2) * 32 + m];
        kss[c] = v;
    }
    __syncthreads();
    float q = bq3[c];
    #pragma unroll 8
    for (int d = 0; d < HID; d++) q += xs[d] * Wq3[(size_t)d*HID + c];
    float qp = fmaxf(q, 0.f) + KEPS;
    qps[c] = qp;
    __syncthreads();
    const int h = c >> 5;
    float den = 0.f;
    #pragma unroll
    for (int m = 0; m < DHEAD; m++) den += qps[h*DHEAD + m] * kss[h*DHEAD + m];
    A0[b*HID + c] = qp / den;
}

__global__ void ta_lastmile(const float* __restrict__ A0, const float* __restrict__ W2f,
                            const float* __restrict__ bo3,
                            const float* __restrict__ ln1s3, const float* __restrict__ ln1b3,
                            const float* __restrict__ W1_3, const float* __restrict__ b1_3,
                            const float* __restrict__ W2_3, const float* __restrict__ b2_3,
                            const float* __restrict__ ln2s3, const float* __restrict__ ln2b3,
                            const float* __restrict__ qpW, const float* __restrict__ qpb,
                            float* __restrict__ out) {
    const int b = blockIdx.x, c = threadIdx.x;
    const int wid = c >> 5, lane = c & 31;
    __shared__ float a0[HID], x1[HID], f[FFD], xo[HID], sred[16];

    a0[c] = A0[b*HID + c];
    __syncthreads();

    float o = bo3[c];
    const float* w = W2f + (size_t)b*HID*HID;
    #pragma unroll 8
    for (int d = 0; d < HID; d++) o += a0[d] * w[(size_t)d*HID + c];
    float v = 2.f * o;

    {
        float s = v, q = v * v;
        #pragma unroll
        for (int off = 16; off; off >>= 1) {
            s += __shfl_xor_sync(0xffffffffu, s, off);
            q += __shfl_xor_sync(0xffffffffu, q, off);
        }
        if (lane == 0) { sred[wid] = s; sred[8 + wid] = q; }
        __syncthreads();
        float ts = 0.f, tq = 0.f;
        #pragma unroll
        for (int i = 0; i < 8; i++) { ts += sred[i]; tq += sred[8 + i]; }
        const float mean = ts * (1.f / HID);
        const float var  = tq * (1.f / HID) - mean * mean;
        const float rr   = rsqrtf(var + LNEPS);
        x1[c] = (v - mean) * rr * ln1s3[c] + ln1b3[c];
        __syncthreads();
    }

    #pragma unroll
    for (int jj = 0; jj < 4; jj++) {
        const int j = c + jj * 256;
        float s = b1_3[j];
        #pragma unroll 8
        for (int d = 0; d < HID; d++) s += x1[d] * W1_3[(size_t)d*FFD + j];
        f[j] = fmaxf(s, 0.f);
    }
    __syncthreads();

    float z = b2_3[c];
    #pragma unroll 8
    for (int j = 0; j < FFD; j++) z += f[j] * W2_3[(size_t)j*HID + c];
    float v2 = 2.f * z;

    {
        float s = v2, q = v2 * v2;
        #pragma unroll
        for (int off = 16; off; off >>= 1) {
            s += __shfl_xor_sync(0xffffffffu, s, off);
            q += __shfl_xor_sync(0xffffffffu, q, off);
        }
        __syncthreads();
        if (lane == 0) { sred[wid] = s; sred[8 + wid] = q; }
        __syncthreads();
        float ts = 0.f, tq = 0.f;
        #pragma unroll
        for (int i = 0; i < 8; i++) { ts += sred[i]; tq += sred[8 + i]; }
        const float mean = ts * (1.f / HID);
        const float var  = tq * (1.f / HID) - mean * mean;
        const float rr   = rsqrtf(var + LNEPS);
        xo[c] = (v2 - mean) * rr * ln2s3[c] + ln2b3[c];
    }
    out[b*HID + c] = xo[c];
    __syncthreads();

    if (c < 32) {
        float s = qpb[c];
        #pragma unroll 8
        for (int d = 0; d < HID; d++) s += xo[d] * qpW[d*32 + c];
        out[BATCH*HID + b*32 + c] = s;
    }
}

// ---------------- launcher ----------------
extern "C" void kernel_launch(void* const* d_in, const int* in_sizes, int n_in,
                              void* d_out, int out_size) {
    const float* hidden = (const float*)d_in[0];
    const float* ins    = (const float*)d_in[1];
    const unsigned char* resets = (const unsigned char*)d_in[2];
    const float* embW = (const float*)d_in[3];
    const float* embb = (const float*)d_in[4];
    const float* Wq = (const float*)d_in[5];
    const float* bq = (const float*)d_in[6];
    const float* Wk = (const float*)d_in[7];
    const float* bk = (const float*)d_in[8];
    const float* Wv = (const float*)d_in[9];
    const float* bv = (const float*)d_in[10];
    const float* Wo = (const float*)d_in[11];
    const float* bo = (const float*)d_in[12];
    const float* ln1s = (const float*)d_in[13];
    const float* ln1b = (const float*)d_in[14];
    const float* W1 = (const float*)d_in[15];
    const float* b1 = (const float*)d_in[16];
    const float* W2 = (const float*)d_in[17];
    const float* b2 = (const float*)d_in[18];
    const float* ln2s = (const float*)d_in[19];
    const float* ln2b = (const float*)d_in[20];
    const float* qpW = (const float*)d_in[21];
    const float* qpb = (const float*)d_in[22];

    fp16 *x, *qkv, *a, *z, *f, *insf, *wt, *we;
    float *kvp, *ksp, *w2f, *a0, *sv, *cv;
    float2 *stats;
    cudaGetSymbolAddress((void**)&x,    g_x);
    cudaGetSymbolAddress((void**)&qkv,  g_qkv);
    cudaGetSymbolAddress((void**)&a,    g_a);
    cudaGetSymbolAddress((void**)&z,    g_z);
    cudaGetSymbolAddress((void**)&f,    g_f);
    cudaGetSymbolAddress((void**)&insf, g_ins);
    cudaGetSymbolAddress((void**)&wt,   g_wt);
    cudaGetSymbolAddress((void**)&we,   g_weffh);
    cudaGetSymbolAddress((void**)&w2f,  g_weff2);
    cudaGetSymbolAddress((void**)&kvp,  g_kvpart);
    cudaGetSymbolAddress((void**)&ksp,  g_kspart);
    cudaGetSymbolAddress((void**)&a0,   g_a0);
    cudaGetSymbolAddress((void**)&sv,   g_sv);
    cudaGetSymbolAddress((void**)&cv,   g_cv);
    cudaGetSymbolAddress((void**)&stats,g_stats);

    const int GEMM_SMEM = 3 * 16384;   // 48KB
    cudaFuncSetAttribute(ta_gemm_f16, cudaFuncAttributeMaxDynamicSharedMemorySize, GEMM_SMEM);

    ta_wconv_all<<<dim3(1024, 25), 256>>>(embW, Wq, Wk, Wv, Wo, W1, W2, ln1s, ln2s, wt);
    ta_snc<<<cdiv(SNC_TOTAL, 256), 256>>>(Wq, Wk, Wv, W1, ln1s, ln1b, ln2s, ln2b, sv, cv);
    {
        int n = BATCH*TLEN*OBSD + BATCH*HID;
        ta_prep<<<cdiv(n,256), 256>>>(ins, hidden, resets, insf, x);
    }
    {
        int M = BATCH * TLEN;
        ta_gemm_f16<<<dim3(HID/128, cdiv(M,128)), 256, GEMM_SMEM>>>(
            insf, wt, embb, embb, embb, sv, cv, stats, x, M, OBSD, HID, 0, 1);
    }

    const dim3 gqkv(QKVW/128, NTOK/128);  // (6, 512)
    const dim3 gkv (4,        NTOK/128);  // kv-only, col tiles 2..5
    const dim3 g256(HID/128,  NTOK/128);  // (2, 512)
    const dim3 gff (FFD/128,  NTOK/128);  // (8, 512)

    for (int l = 0; l < NLAY; l++) {
        const bool last = (l == NLAY - 1);
        size_t base = WT_EMB_SZ + (size_t)l * WT_LAYER_SZ;
        const fp16 *qkvw = wt + base;
        const fp16 *w1t  = wt + base + 262144;
        const fp16 *w2t  = wt + base + 524288;
        const float *svq = sv + 3*FFD + (l-1)*QKVW;
        const float *cvq = cv + 3*FFD + (l-1)*QKVW;

        if (!last) {
            if (l == 0) {
                ta_gemm_f16<<<gqkv, 256, GEMM_SMEM>>>(x, qkvw,
                                                      bq + l*HID, bk + l*HID, bv + l*HID,
                                                      sv, cv, stats,
                                                      qkv, NTOK, HID, QKVW, 0, 2);
            } else {
                ta_gemm_f16<<<gqkv, 256, GEMM_SMEM>>>(z, qkvw,
                                                      bq + l*HID, bk + l*HID, bv + l*HID,
                                                      svq, cvq, stats,
                                                      qkv, NTOK, HID, QKVW, 0, 2 | 64);
            }
        } else {
            ta_gemm_f16<<<gkv, 256, GEMM_SMEM>>>(z, qkvw,
                                                 bq + l*HID, bk + l*HID, bv + l*HID,
                                                 svq, cvq, stats,
                                                 qkv, NTOK, HID, QKVW, 0, 2 | 8 | 64);
        }
        ta_kv_reduce<<<dim3(KSPLIT, NHEAD, BATCH), 256>>>(qkv, kvp, ksp);
        ta_weff<<<dim3(NHEAD, BATCH), 256>>>(kvp, Wo + (size_t)l*HID*HID, we, w2f);

        if (!last) {
            ta_qpscale<<<dim3(LSEQ/32, BATCH), 256>>>(qkv, ksp, a);
            ta_gemm_f16<<<g256, 256, GEMM_SMEM>>>(a, we,
                                                  bo + l*HID, bo + l*HID, bo + l*HID,
                                                  sv, cv, stats,
                                                  z, NTOK, HID, HID, 0, 4 | 32);
            ta_gemm_f16<<<gff, 256, GEMM_SMEM>>>(z, w1t,
                                                 b1 + l*FFD, b1 + l*FFD, b1 + l*FFD,
                                                 sv + l*FFD, cv + l*FFD, stats,
                                                 f, NTOK, HID, FFD, 2, 64);
            ta_gemm_f16<<<g256, 256, GEMM_SMEM>>>(f, w2t,
                                                  b2 + l*HID, b2 + l*HID, b2 + l*HID,
                                                  sv, cv, stats,
                                                  z, NTOK, FFD, HID, 0, 32);
        } else {
            ta_lastq<<<BATCH, 256>>>(z, stats, ln2s + 2*HID, ln2b + 2*HID,
                                     Wq + (size_t)l*HID*HID, bq + l*HID, ksp, a0);
            ta_lastmile<<<BATCH, 256>>>(a0, w2f, bo + l*HID,
                                        ln1s + l*HID, ln1b + l*HID,
                                        W1 + (size_t)l*HID*FFD, b1 + l*FFD,
                                        W2 + (size_t)l*FFD*HID, b2 + l*HID,
                                        ln2s + l*HID, ln2b + l*HID,
                                        qpW, qpb, (float*)d_out);
        }
    }
}